// round 8
// baseline (speedup 1.0000x reference)
#include <cuda_runtime.h>
#include <math.h>
#include <stdint.h>

#define N_NODES 50000
#define N_EDGES 800000
#define NFEAT   512
#define NHID    128
#define NCLASS  64

// Scratch (allocation-free)
__device__ float g_h0[(size_t)N_NODES * NHID];
__device__ float g_h1[(size_t)N_NODES * NHID];
__device__ uint16_t g_w1t_hi[NHID * NFEAT];   // W1^T hi fp16 [n][k]
__device__ uint16_t g_w1t_lo[NHID * NFEAT];   // W1^T lo fp16 [n][k]
__device__ uint16_t g_w2t_hi[NCLASS * NHID];  // W2^T hi bf16 [n][k]
__device__ uint16_t g_w2t_lo[NCLASS * NHID];  // W2^T lo bf16 [n][k]
__device__ int g_rowptr[N_NODES + 1];

// ---------------------------------------------------------------------------
// helpers
// ---------------------------------------------------------------------------
__device__ __forceinline__ uint32_t smem_u32(const void* p) {
    uint32_t a;
    asm("{ .reg .u64 t; cvta.to.shared.u64 t, %1; cvt.u32.u64 %0, t; }" : "=r"(a) : "l"(p));
    return a;
}
// bf16 pack (first arg -> low 16)
__device__ __forceinline__ uint32_t pack_bf16x2(float lo, float hi) {
    uint32_t r;
    asm("cvt.rn.bf16x2.f32 %0, %1, %2;" : "=r"(r) : "f"(hi), "f"(lo));
    return r;
}
__device__ __forceinline__ float bf_lo_f32(uint32_t p) { return __uint_as_float(p << 16); }
__device__ __forceinline__ float bf_hi_f32(uint32_t p) { return __uint_as_float(p & 0xFFFF0000u); }
// fp16 pack (first arg -> low 16)
__device__ __forceinline__ uint32_t pack_f16x2(float lo, float hi) {
    uint32_t r;
    asm("cvt.rn.f16x2.f32 %0, %1, %2;" : "=r"(r) : "f"(hi), "f"(lo));
    return r;
}
__device__ __forceinline__ float f16_lo_f32(uint32_t p) {
    float f; asm("{ .reg .f16 h; mov.b32 {h, _}, %1; cvt.f32.f16 %0, h; }" : "=f"(f) : "r"(p));
    return f;
}
__device__ __forceinline__ float f16_hi_f32(uint32_t p) {
    float f; asm("{ .reg .f16 h; mov.b32 {_, h}, %1; cvt.f32.f16 %0, h; }" : "=f"(f) : "r"(p));
    return f;
}

__device__ __forceinline__ void mma_bf16(float* d, const uint32_t* a,
                                         uint32_t b0, uint32_t b1) {
    asm("mma.sync.aligned.m16n8k16.row.col.f32.bf16.bf16.f32 "
        "{%0,%1,%2,%3}, {%4,%5,%6,%7}, {%8,%9}, {%0,%1,%2,%3};"
        : "+f"(d[0]), "+f"(d[1]), "+f"(d[2]), "+f"(d[3])
        : "r"(a[0]), "r"(a[1]), "r"(a[2]), "r"(a[3]), "r"(b0), "r"(b1));
}
__device__ __forceinline__ void mma_f16(float* d, const uint32_t* a,
                                        uint32_t b0, uint32_t b1) {
    asm("mma.sync.aligned.m16n8k16.row.col.f32.f16.f16.f32 "
        "{%0,%1,%2,%3}, {%4,%5,%6,%7}, {%8,%9}, {%0,%1,%2,%3};"
        : "+f"(d[0]), "+f"(d[1]), "+f"(d[2]), "+f"(d[3])
        : "r"(a[0]), "r"(a[1]), "r"(a[2]), "r"(a[3]), "r"(b0), "r"(b1));
}
__device__ __forceinline__ void cp_async16(uint32_t dst, const void* src) {
    asm volatile("cp.async.cg.shared.global [%0], [%1], 16;" :: "r"(dst), "l"(src));
}
#define CP_COMMIT() asm volatile("cp.async.commit_group;" ::: "memory")
#define CP_WAIT0()  asm volatile("cp.async.wait_group 0;" ::: "memory")

// ---------------------------------------------------------------------------
// prep kernels
// ---------------------------------------------------------------------------
__global__ void prep_w1_kernel(const float* __restrict__ W1) {
    int idx = blockIdx.x * 256 + threadIdx.x;
    if (idx >= NHID * NFEAT / 2) return;
    int n = idx >> 8;
    int k2 = (idx & 255) * 2;
    float w0 = W1[(size_t)k2 * NHID + n];
    float w1 = W1[(size_t)(k2 + 1) * NHID + n];
    uint32_t ph = pack_f16x2(w0, w1);
    uint32_t pl = pack_f16x2(w0 - f16_lo_f32(ph), w1 - f16_hi_f32(ph));
    *(uint32_t*)&g_w1t_hi[n * NFEAT + k2] = ph;
    *(uint32_t*)&g_w1t_lo[n * NFEAT + k2] = pl;
}

__global__ void prep_w2_kernel(const float* __restrict__ W2) {
    int idx = blockIdx.x * 256 + threadIdx.x;
    if (idx >= NCLASS * NHID / 2) return;
    int n = idx >> 6;
    int k2 = (idx & 63) * 2;
    float w0 = W2[(size_t)k2 * NCLASS + n];
    float w1 = W2[(size_t)(k2 + 1) * NCLASS + n];
    uint32_t ph = pack_bf16x2(w0, w1);
    uint32_t pl = pack_bf16x2(w0 - bf_lo_f32(ph), w1 - bf_hi_f32(ph));
    *(uint32_t*)&g_w2t_hi[n * NHID + k2] = ph;
    *(uint32_t*)&g_w2t_lo[n * NHID + k2] = pl;
}

__global__ void rowptr_kernel(const int* __restrict__ rows) {
    int e = blockIdx.x * 256 + threadIdx.x;
    if (e >= N_EDGES) return;
    int r = rows[e];
    int rp = (e == 0) ? -1 : rows[e - 1];
    for (int q = rp + 1; q <= r; ++q) g_rowptr[q] = e;
    if (e == N_EDGES - 1)
        for (int q = r + 1; q <= N_NODES; ++q) g_rowptr[q] = N_EDGES;
}

// ---------------------------------------------------------------------------
// GEMM1: fp16 2-term (A=fp16(X), B=W1^T hi+lo fp16).
// CTA 64x128, 128 threads, 4 warps (2M x 2N), warp tile 32x64. BK=32,
// double-buffered, 4 CTAs/SM. Pitch 40 (conflict-free).
// Buffer: A 64x40 | Bh 128x40 | Bl 128x40 = 12800 elems = 25600 B; x2 = 51200.
// ---------------------------------------------------------------------------
#define LDA   40
#define SA    0
#define SBH   2560
#define SBL   7680
#define BUFE  12800
#define SMEM_G1_BYTES (2 * BUFE * 2)   // 51200

__global__ __launch_bounds__(128, 4) void gemm1_mma_kernel(const float* __restrict__ x,
                                                           float* __restrict__ out)
{
    extern __shared__ uint16_t sm[];
    const uint32_t smb = smem_u32(sm);

    const int tid  = threadIdx.x;
    const int wid  = tid >> 5;
    const int lane = tid & 31;
    const int m0   = blockIdx.x * 64;
    const int wm = (wid >> 1) * 32;   // 0 / 32
    const int wn = (wid & 1) * 64;    // 0 / 64

    float acc[2][8][4];
#pragma unroll
    for (int i = 0; i < 2; i++)
#pragma unroll
        for (int j = 0; j < 8; j++)
#pragma unroll
            for (int q = 0; q < 4; q++) acc[i][j][q] = 0.f;

    // A staging: thread -> (row = tid&63, half = tid>>6), 16 k each
    const int arow  = tid & 63;
    const int ahalf = tid >> 6;
    int rg = m0 + arow;
    if (rg >= N_NODES) rg = N_NODES - 1;
    const float* xrow = x + (size_t)rg * NFEAT + ahalf * 16;
    const int dstA = SA + arow * LDA + ahalf * 16;

    // B staging: thread -> n-row = tid, 32 k per chunk, hi + lo
    const uint16_t* bhrow = g_w1t_hi + (size_t)tid * NFEAT;
    const uint16_t* blrow = g_w1t_lo + (size_t)tid * NFEAT;
    const int dstB = tid * LDA;

    float4 xa[4];

#define COPY_B(c, buf) do {                                                   \
        uint32_t dh = smb + ((buf) * BUFE + SBH + dstB) * 2;                  \
        uint32_t dl = smb + ((buf) * BUFE + SBL + dstB) * 2;                  \
        _Pragma("unroll")                                                     \
        for (int j = 0; j < 4; ++j) {                                         \
            cp_async16(dh + j * 16, bhrow + (c) * 32 + j * 8);                \
            cp_async16(dl + j * 16, blrow + (c) * 32 + j * 8);                \
        }                                                                     \
        CP_COMMIT();                                                          \
    } while (0)

#define LOAD_A(c) do {                                                        \
        _Pragma("unroll")                                                     \
        for (int j = 0; j < 4; ++j)                                           \
            xa[j] = *(const float4*)(xrow + (c) * 32 + j * 4);                \
    } while (0)

#define CONV_STORE_A(buf) do {                                                \
        uint32_t H[8];                                                        \
        _Pragma("unroll")                                                     \
        for (int j = 0; j < 4; ++j) {                                         \
            H[2*j]   = pack_f16x2(xa[j].x, xa[j].y);                          \
            H[2*j+1] = pack_f16x2(xa[j].z, xa[j].w);                          \
        }                                                                     \
        uint16_t* dh = sm + (buf) * BUFE + dstA;                              \
        *(uint4*)(dh)     = *(uint4*)&H[0];                                   \
        *(uint4*)(dh + 8) = *(uint4*)&H[4];                                   \
    } while (0)

    COPY_B(0, 0);
    LOAD_A(0);
    CONV_STORE_A(0);
    CP_WAIT0();
    __syncthreads();

    for (int c = 0; c < 16; ++c) {
        const int cur = c & 1, nxt = cur ^ 1;
        if (c < 15) { COPY_B(c + 1, nxt); LOAD_A(c + 1); }

        const uint16_t* base = sm + cur * BUFE;
#pragma unroll
        for (int ks = 0; ks < 2; ++ks) {
            const int kk = ks * 16;
            uint32_t a[2][4];
#pragma unroll
            for (int mt = 0; mt < 2; ++mt) {
                int r = wm + mt * 16 + (lane >> 2);
                int cc = kk + (lane & 3) * 2;
                a[mt][0] = *(const uint32_t*)(base + SA + r * LDA + cc);
                a[mt][1] = *(const uint32_t*)(base + SA + (r + 8) * LDA + cc);
                a[mt][2] = *(const uint32_t*)(base + SA + r * LDA + cc + 8);
                a[mt][3] = *(const uint32_t*)(base + SA + (r + 8) * LDA + cc + 8);
            }
#pragma unroll
            for (int nt = 0; nt < 8; ++nt) {
                int n = wn + nt * 8 + (lane >> 2);
                int kq = kk + (lane & 3) * 2;
                uint32_t bh0 = *(const uint32_t*)(base + SBH + n * LDA + kq);
                uint32_t bh1 = *(const uint32_t*)(base + SBH + n * LDA + kq + 8);
                uint32_t bl0 = *(const uint32_t*)(base + SBL + n * LDA + kq);
                uint32_t bl1 = *(const uint32_t*)(base + SBL + n * LDA + kq + 8);
#pragma unroll
                for (int mt = 0; mt < 2; ++mt) {
                    mma_f16(acc[mt][nt], a[mt], bh0, bh1);
                    mma_f16(acc[mt][nt], a[mt], bl0, bl1);
                }
            }
        }

        if (c < 15) { CONV_STORE_A(nxt); CP_WAIT0(); }
        __syncthreads();
    }

#pragma unroll
    for (int mt = 0; mt < 2; ++mt) {
        int r0 = m0 + wm + mt * 16 + (lane >> 2);
        int r1 = r0 + 8;
#pragma unroll
        for (int nt = 0; nt < 8; ++nt) {
            int cc = wn + nt * 8 + (lane & 3) * 2;
            if (r0 < N_NODES)
                *(float2*)(out + (size_t)r0 * NHID + cc) = make_float2(acc[mt][nt][0], acc[mt][nt][1]);
            if (r1 < N_NODES)
                *(float2*)(out + (size_t)r1 * NHID + cc) = make_float2(acc[mt][nt][2], acc[mt][nt][3]);
        }
    }
}

// ---------------------------------------------------------------------------
// SpMM: warp per row, row_ptr, 4-edge unroll.
// ---------------------------------------------------------------------------
template <bool RELU>
__global__ __launch_bounds__(256) void spmm_kernel(const int* __restrict__ cols,
                                                   const float* __restrict__ vals,
                                                   const float* __restrict__ hin,
                                                   const float* __restrict__ bias,
                                                   float* __restrict__ hout)
{
    const int gw   = (blockIdx.x * blockDim.x + threadIdx.x) >> 5;
    const int lane = threadIdx.x & 31;
    if (gw >= N_NODES) return;

    const int start = g_rowptr[gw];
    const int end   = g_rowptr[gw + 1];

    float ax = 0.f, ay = 0.f, az = 0.f, aw = 0.f;
    int e = start;
    for (; e + 4 <= end; e += 4) {
        int   c0 = cols[e],     c1 = cols[e + 1], c2 = cols[e + 2], c3 = cols[e + 3];
        float v0 = vals[e],     v1 = vals[e + 1], v2 = vals[e + 2], v3 = vals[e + 3];
        float4 h0 = *(const float4*)(hin + (size_t)c0 * NHID + lane * 4);
        float4 h1 = *(const float4*)(hin + (size_t)c1 * NHID + lane * 4);
        float4 h2 = *(const float4*)(hin + (size_t)c2 * NHID + lane * 4);
        float4 h3 = *(const float4*)(hin + (size_t)c3 * NHID + lane * 4);
        ax = fmaf(v0, h0.x, ax); ay = fmaf(v0, h0.y, ay);
        az = fmaf(v0, h0.z, az); aw = fmaf(v0, h0.w, aw);
        ax = fmaf(v1, h1.x, ax); ay = fmaf(v1, h1.y, ay);
        az = fmaf(v1, h1.z, az); aw = fmaf(v1, h1.w, aw);
        ax = fmaf(v2, h2.x, ax); ay = fmaf(v2, h2.y, ay);
        az = fmaf(v2, h2.z, az); aw = fmaf(v2, h2.w, aw);
        ax = fmaf(v3, h3.x, ax); ay = fmaf(v3, h3.y, ay);
        az = fmaf(v3, h3.z, az); aw = fmaf(v3, h3.w, aw);
    }
    for (; e < end; ++e) {
        int   c0 = cols[e];
        float v0 = vals[e];
        float4 h0 = *(const float4*)(hin + (size_t)c0 * NHID + lane * 4);
        ax = fmaf(v0, h0.x, ax); ay = fmaf(v0, h0.y, ay);
        az = fmaf(v0, h0.z, az); aw = fmaf(v0, h0.w, aw);
    }
    if (RELU) {
        float4 b = ((const float4*)bias)[lane];
        ax = fmaxf(ax + b.x, 0.f); ay = fmaxf(ay + b.y, 0.f);
        az = fmaxf(az + b.z, 0.f); aw = fmaxf(aw + b.w, 0.f);
    }
    *(float4*)(hout + (size_t)gw * NHID + lane * 4) = make_float4(ax, ay, az, aw);
}

// ---------------------------------------------------------------------------
// GEMM2 via mma.sync bf16 split + fused bias + log_softmax. (R6, kept)
// ---------------------------------------------------------------------------
#define LDH 136
#define G2_SHH 0
#define G2_SHL 8704
#define G2_SWH 17408
#define G2_SWL 26112
#define SMEM_G2_BYTES (34816 * 2)

__global__ __launch_bounds__(128) void gemm2_mma_kernel(const float* __restrict__ h,
                                                        const float* __restrict__ b2,
                                                        float* __restrict__ out)
{
    extern __shared__ uint16_t s2[];

    const int tid  = threadIdx.x;
    const int lane = tid & 31;
    const int wid  = tid >> 5;
    const int r0   = blockIdx.x * 64;

    const int row = tid >> 1, half = tid & 1;
    int rg = r0 + row;
    if (rg >= N_NODES) rg = N_NODES - 1;
    const float* hrow = h + (size_t)rg * NHID + half * 64;
#pragma unroll
    for (int g = 0; g < 2; ++g) {
        uint32_t H[16], L[16];
#pragma unroll
        for (int j = 0; j < 8; ++j) {
            float4 v = *(const float4*)(hrow + g * 32 + j * 4);
            uint32_t p0 = pack_bf16x2(v.x, v.y);
            uint32_t p1 = pack_bf16x2(v.z, v.w);
            H[2 * j]     = p0;
            H[2 * j + 1] = p1;
            L[2 * j]     = pack_bf16x2(v.x - bf_lo_f32(p0), v.y - bf_hi_f32(p0));
            L[2 * j + 1] = pack_bf16x2(v.z - bf_lo_f32(p1), v.w - bf_hi_f32(p1));
        }
        uint16_t* dh = s2 + G2_SHH + row * LDH + half * 64 + g * 32;
        uint16_t* dl = s2 + G2_SHL + row * LDH + half * 64 + g * 32;
#pragma unroll
        for (int j = 0; j < 4; ++j) {
            *(uint4*)(dh + j * 8) = *(uint4*)&H[j * 4];
            *(uint4*)(dl + j * 8) = *(uint4*)&L[j * 4];
        }
    }

    {
        const int n = tid >> 1;
        const uint16_t* wh = g_w2t_hi + n * NHID + half * 64;
        const uint16_t* wl = g_w2t_lo + n * NHID + half * 64;
        uint16_t* dh = s2 + G2_SWH + n * LDH + half * 64;
        uint16_t* dl = s2 + G2_SWL + n * LDH + half * 64;
#pragma unroll
        for (int j = 0; j < 8; ++j) {
            *(uint4*)(dh + j * 8) = *(const uint4*)(wh + j * 8);
            *(uint4*)(dl + j * 8) = *(const uint4*)(wl + j * 8);
        }
    }
    __syncthreads();

    float acc[8][4];
#pragma unroll
    for (int nt = 0; nt < 8; ++nt)
#pragma unroll
        for (int q = 0; q < 4; ++q) acc[nt][q] = 0.f;

    const int wr = wid * 16;
#pragma unroll
    for (int ks = 0; ks < 8; ++ks) {
        const int kk = ks * 16;
        const int r  = wr + (lane >> 2);
        const int cc = kk + (lane & 3) * 2;
        uint32_t a_hi[4], a_lo[4];
        a_hi[0] = *(const uint32_t*)(s2 + G2_SHH + r * LDH + cc);
        a_hi[1] = *(const uint32_t*)(s2 + G2_SHH + (r + 8) * LDH + cc);
        a_hi[2] = *(const uint32_t*)(s2 + G2_SHH + r * LDH + cc + 8);
        a_hi[3] = *(const uint32_t*)(s2 + G2_SHH + (r + 8) * LDH + cc + 8);
        a_lo[0] = *(const uint32_t*)(s2 + G2_SHL + r * LDH + cc);
        a_lo[1] = *(const uint32_t*)(s2 + G2_SHL + (r + 8) * LDH + cc);
        a_lo[2] = *(const uint32_t*)(s2 + G2_SHL + r * LDH + cc + 8);
        a_lo[3] = *(const uint32_t*)(s2 + G2_SHL + (r + 8) * LDH + cc + 8);
#pragma unroll
        for (int nt = 0; nt < 8; ++nt) {
            int n  = nt * 8 + (lane >> 2);
            int kq = kk + (lane & 3) * 2;
            uint32_t bh0 = *(const uint32_t*)(s2 + G2_SWH + n * LDH + kq);
            uint32_t bh1 = *(const uint32_t*)(s2 + G2_SWH + n * LDH + kq + 8);
            uint32_t bl0 = *(const uint32_t*)(s2 + G2_SWL + n * LDH + kq);
            uint32_t bl1 = *(const uint32_t*)(s2 + G2_SWL + n * LDH + kq + 8);
            mma_bf16(acc[nt], a_hi, bh0, bh1);
            mma_bf16(acc[nt], a_hi, bl0, bl1);
            mma_bf16(acc[nt], a_lo, bh0, bh1);
        }
    }

#pragma unroll
    for (int nt = 0; nt < 8; ++nt) {
        int c = nt * 8 + (lane & 3) * 2;
        float bb0 = b2[c], bb1 = b2[c + 1];
        acc[nt][0] += bb0; acc[nt][1] += bb1;
        acc[nt][2] += bb0; acc[nt][3] += bb1;
    }

    float m0 = -1e30f, m1 = -1e30f;
#pragma unroll
    for (int nt = 0; nt < 8; ++nt) {
        m0 = fmaxf(m0, fmaxf(acc[nt][0], acc[nt][1]));
        m1 = fmaxf(m1, fmaxf(acc[nt][2], acc[nt][3]));
    }
    m0 = fmaxf(m0, __shfl_xor_sync(0xffffffffu, m0, 1));
    m0 = fmaxf(m0, __shfl_xor_sync(0xffffffffu, m0, 2));
    m1 = fmaxf(m1, __shfl_xor_sync(0xffffffffu, m1, 1));
    m1 = fmaxf(m1, __shfl_xor_sync(0xffffffffu, m1, 2));

    float s0 = 0.f, s1 = 0.f;
#pragma unroll
    for (int nt = 0; nt < 8; ++nt) {
        s0 += expf(acc[nt][0] - m0) + expf(acc[nt][1] - m0);
        s1 += expf(acc[nt][2] - m1) + expf(acc[nt][3] - m1);
    }
    s0 += __shfl_xor_sync(0xffffffffu, s0, 1);
    s0 += __shfl_xor_sync(0xffffffffu, s0, 2);
    s1 += __shfl_xor_sync(0xffffffffu, s1, 1);
    s1 += __shfl_xor_sync(0xffffffffu, s1, 2);
    const float lse0 = m0 + logf(s0);
    const float lse1 = m1 + logf(s1);

    const int row0 = r0 + wr + (lane >> 2);
    const int row1 = row0 + 8;
#pragma unroll
    for (int nt = 0; nt < 8; ++nt) {
        int c = nt * 8 + (lane & 3) * 2;
        if (row0 < N_NODES)
            *(float2*)(out + (size_t)row0 * NCLASS + c) =
                make_float2(acc[nt][0] - lse0, acc[nt][1] - lse0);
        if (row1 < N_NODES)
            *(float2*)(out + (size_t)row1 * NCLASS + c) =
                make_float2(acc[nt][2] - lse1, acc[nt][3] - lse1);
    }
}

// ---------------------------------------------------------------------------
extern "C" void kernel_launch(void* const* d_in, const int* in_sizes, int n_in,
                              void* d_out, int out_size)
{
    const float* x    = (const float*)d_in[0];
    const int*   rows = (const int*)  d_in[1];
    const int*   cols = (const int*)  d_in[2];
    const float* vals = (const float*)d_in[3];
    const float* W1   = (const float*)d_in[4];
    const float* b1   = (const float*)d_in[5];
    const float* W2   = (const float*)d_in[6];
    const float* b2   = (const float*)d_in[7];
    float* out = (float*)d_out;

    float *h0, *h1;
    cudaGetSymbolAddress((void**)&h0, g_h0);
    cudaGetSymbolAddress((void**)&h1, g_h1);

    cudaFuncSetAttribute(gemm1_mma_kernel, cudaFuncAttributeMaxDynamicSharedMemorySize, SMEM_G1_BYTES);
    cudaFuncSetAttribute(gemm2_mma_kernel, cudaFuncAttributeMaxDynamicSharedMemorySize, SMEM_G2_BYTES);

    // 0) prep
    prep_w1_kernel<<<(NHID * NFEAT / 2 + 255) / 256, 256>>>(W1);
    prep_w2_kernel<<<(NCLASS * NHID / 2 + 255) / 256, 256>>>(W2);
    rowptr_kernel<<<(N_EDGES + 255) / 256, 256>>>(rows);

    // 1) h0 = X @ W1  (fp16 2-term)
    gemm1_mma_kernel<<<(N_NODES + 63) / 64, 128, SMEM_G1_BYTES>>>(x, h0);

    // 2) h1 = relu(A @ h0 + b1)
    const int spmm_blocks = (N_NODES * 32 + 255) / 256;
    spmm_kernel<true><<<spmm_blocks, 256>>>(cols, vals, h0, b1, h1);

    // 3) h0 <- A @ h1
    spmm_kernel<false><<<spmm_blocks, 256>>>(cols, vals, h1, b1, h0);

    // 4) out = logsoftmax(h0 @ W2 + b2)
    gemm2_mma_kernel<<<(N_NODES + 63) / 64, 128, SMEM_G2_BYTES>>>(h0, b2, out);
}

// round 9
// speedup vs baseline: 1.1774x; 1.1774x over previous
#include <cuda_runtime.h>
#include <math.h>
#include <stdint.h>

#define N_NODES 50000
#define N_EDGES 800000
#define NFEAT   512
#define NHID    128
#define NCLASS  64

// Scratch (allocation-free)
__device__ float g_h0[(size_t)N_NODES * NHID];
__device__ float g_h1[(size_t)N_NODES * NHID];
__device__ uint16_t g_w1t_hi[NHID * NFEAT];   // W1^T hi fp16 [n][k]
__device__ uint16_t g_w1t_lo[NHID * NFEAT];   // W1^T lo fp16 [n][k]
__device__ uint16_t g_w2t_hi[NCLASS * NHID];  // W2^T hi bf16 [n][k]
__device__ uint16_t g_w2t_lo[NCLASS * NHID];  // W2^T lo bf16 [n][k]
__device__ int g_rowptr[N_NODES + 1];

// ---------------------------------------------------------------------------
// helpers
// ---------------------------------------------------------------------------
__device__ __forceinline__ uint32_t smem_u32(const void* p) {
    uint32_t a;
    asm("{ .reg .u64 t; cvta.to.shared.u64 t, %1; cvt.u32.u64 %0, t; }" : "=r"(a) : "l"(p));
    return a;
}
__device__ __forceinline__ uint32_t pack_bf16x2(float lo, float hi) {
    uint32_t r;
    asm("cvt.rn.bf16x2.f32 %0, %1, %2;" : "=r"(r) : "f"(hi), "f"(lo));
    return r;
}
__device__ __forceinline__ float bf_lo_f32(uint32_t p) { return __uint_as_float(p << 16); }
__device__ __forceinline__ float bf_hi_f32(uint32_t p) { return __uint_as_float(p & 0xFFFF0000u); }
__device__ __forceinline__ uint32_t pack_f16x2(float lo, float hi) {
    uint32_t r;
    asm("cvt.rn.f16x2.f32 %0, %1, %2;" : "=r"(r) : "f"(hi), "f"(lo));
    return r;
}
__device__ __forceinline__ float f16_lo_f32(uint32_t p) {
    float f; asm("{ .reg .f16 h; mov.b32 {h, _}, %1; cvt.f32.f16 %0, h; }" : "=f"(f) : "r"(p));
    return f;
}
__device__ __forceinline__ float f16_hi_f32(uint32_t p) {
    float f; asm("{ .reg .f16 h; mov.b32 {_, h}, %1; cvt.f32.f16 %0, h; }" : "=f"(f) : "r"(p));
    return f;
}

__device__ __forceinline__ void mma_bf16(float* d, const uint32_t* a,
                                         uint32_t b0, uint32_t b1) {
    asm("mma.sync.aligned.m16n8k16.row.col.f32.bf16.bf16.f32 "
        "{%0,%1,%2,%3}, {%4,%5,%6,%7}, {%8,%9}, {%0,%1,%2,%3};"
        : "+f"(d[0]), "+f"(d[1]), "+f"(d[2]), "+f"(d[3])
        : "r"(a[0]), "r"(a[1]), "r"(a[2]), "r"(a[3]), "r"(b0), "r"(b1));
}
__device__ __forceinline__ void mma_f16(float* d, const uint32_t* a,
                                        uint32_t b0, uint32_t b1) {
    asm("mma.sync.aligned.m16n8k16.row.col.f32.f16.f16.f32 "
        "{%0,%1,%2,%3}, {%4,%5,%6,%7}, {%8,%9}, {%0,%1,%2,%3};"
        : "+f"(d[0]), "+f"(d[1]), "+f"(d[2]), "+f"(d[3])
        : "r"(a[0]), "r"(a[1]), "r"(a[2]), "r"(a[3]), "r"(b0), "r"(b1));
}
__device__ __forceinline__ void cp_async16(uint32_t dst, const void* src) {
    asm volatile("cp.async.cg.shared.global [%0], [%1], 16;" :: "r"(dst), "l"(src));
}
#define CP_COMMIT() asm volatile("cp.async.commit_group;" ::: "memory")
#define CP_WAIT0()  asm volatile("cp.async.wait_group 0;" ::: "memory")

// ---------------------------------------------------------------------------
// prep kernels
// ---------------------------------------------------------------------------
__global__ void prep_w1_kernel(const float* __restrict__ W1) {
    int idx = blockIdx.x * 256 + threadIdx.x;
    if (idx >= NHID * NFEAT / 2) return;
    int n = idx >> 8;
    int k2 = (idx & 255) * 2;
    float w0 = W1[(size_t)k2 * NHID + n];
    float w1 = W1[(size_t)(k2 + 1) * NHID + n];
    uint32_t ph = pack_f16x2(w0, w1);
    uint32_t pl = pack_f16x2(w0 - f16_lo_f32(ph), w1 - f16_hi_f32(ph));
    *(uint32_t*)&g_w1t_hi[n * NFEAT + k2] = ph;
    *(uint32_t*)&g_w1t_lo[n * NFEAT + k2] = pl;
}

__global__ void prep_w2_kernel(const float* __restrict__ W2) {
    int idx = blockIdx.x * 256 + threadIdx.x;
    if (idx >= NCLASS * NHID / 2) return;
    int n = idx >> 6;
    int k2 = (idx & 63) * 2;
    float w0 = W2[(size_t)k2 * NCLASS + n];
    float w1 = W2[(size_t)(k2 + 1) * NCLASS + n];
    uint32_t ph = pack_bf16x2(w0, w1);
    uint32_t pl = pack_bf16x2(w0 - bf_lo_f32(ph), w1 - bf_hi_f32(ph));
    *(uint32_t*)&g_w2t_hi[n * NHID + k2] = ph;
    *(uint32_t*)&g_w2t_lo[n * NHID + k2] = pl;
}

__global__ void rowptr_kernel(const int* __restrict__ rows) {
    int e = blockIdx.x * 256 + threadIdx.x;
    if (e >= N_EDGES) return;
    int r = rows[e];
    int rp = (e == 0) ? -1 : rows[e - 1];
    for (int q = rp + 1; q <= r; ++q) g_rowptr[q] = e;
    if (e == N_EDGES - 1)
        for (int q = r + 1; q <= N_NODES; ++q) g_rowptr[q] = N_EDGES;
}

// ---------------------------------------------------------------------------
// GEMM1: fp16 2-term (A=fp16(X) in-kernel, B=W1^T hi+lo fp16 prepped).
// CTA 128x128, 256 threads, 8 warps (4M x 2N), warp tile 32x64, BK=32.
// A streamed as RAW fp32 via cp.async into staging (pitch 36 fl, conflict-
// free), converted SMEM->SMEM off the DRAM critical path. Double-buffered.
// SMEM: fp16 bufs 2x30720B + fp32 staging 2x18432B = 98304 B -> 2 CTAs/SM.
// ---------------------------------------------------------------------------
#define LDA   40       // fp16 pitch
#define SA    0
#define SBH   5120
#define SBL   10240
#define BUFE  15360    // fp16 elems per buffer
#define LDAF  36       // fp32 staging pitch (floats)
#define STAGF 4608     // floats per staging buffer (128*36)
#define SMEM_G1_BYTES (2 * BUFE * 2 + 2 * STAGF * 4)   // 98304

__global__ __launch_bounds__(256, 2) void gemm1_mma_kernel(const float* __restrict__ x,
                                                           float* __restrict__ out)
{
    extern __shared__ uint16_t sm[];
    float* stag = (float*)(sm + 2 * BUFE);
    const uint32_t smb = smem_u32(sm);
    const uint32_t stb = smem_u32(stag);

    const int tid  = threadIdx.x;
    const int wid  = tid >> 5;
    const int lane = tid & 31;
    const int m0   = blockIdx.x * 128;
    const int wm = (wid >> 1) * 32;   // 0,32,64,96
    const int wn = (wid & 1) * 64;    // 0,64

    float acc[2][8][4];
#pragma unroll
    for (int i = 0; i < 2; i++)
#pragma unroll
        for (int j = 0; j < 8; j++)
#pragma unroll
            for (int q = 0; q < 4; q++) acc[i][j][q] = 0.f;

    // staging mapping: thread -> (row = tid>>1, half = tid&1) -> 16 values
    const int arow  = tid >> 1;       // 0..127
    const int ahalf = tid & 1;        // 0/1
    int rg = m0 + arow;
    if (rg >= N_NODES) rg = N_NODES - 1;
    const float* xrow = x + (size_t)rg * NFEAT + ahalf * 16;
    const uint16_t* bhrow = g_w1t_hi + (size_t)arow * NFEAT + ahalf * 16;
    const uint16_t* blrow = g_w1t_lo + (size_t)arow * NFEAT + ahalf * 16;
    const int stA  = arow * LDAF + ahalf * 16;           // fp32 elems
    const int dstA = SA  + arow * LDA + ahalf * 16;      // fp16 elems
    const int dstB = arow * LDA + ahalf * 16;            // fp16 elems (n-row = arow)

#define COPY_AB(c, buf) do {                                                  \
        uint32_t da = stb + ((buf) * STAGF + stA) * 4;                        \
        _Pragma("unroll")                                                     \
        for (int j = 0; j < 4; ++j)                                           \
            cp_async16(da + j * 16, xrow + (c) * 32 + j * 4);                 \
        uint32_t dh = smb + ((buf) * BUFE + SBH + dstB) * 2;                  \
        uint32_t dl = smb + ((buf) * BUFE + SBL + dstB) * 2;                  \
        _Pragma("unroll")                                                     \
        for (int j = 0; j < 2; ++j) {                                         \
            cp_async16(dh + j * 16, bhrow + (c) * 32 + j * 8);                \
            cp_async16(dl + j * 16, blrow + (c) * 32 + j * 8);                \
        }                                                                     \
        CP_COMMIT();                                                          \
    } while (0)

#define CONV_A(buf) do {                                                      \
        const float* sf = stag + (buf) * STAGF + stA;                         \
        float4 v0 = *(const float4*)(sf);                                     \
        float4 v1 = *(const float4*)(sf + 4);                                 \
        float4 v2 = *(const float4*)(sf + 8);                                 \
        float4 v3 = *(const float4*)(sf + 12);                                \
        uint32_t H[8];                                                        \
        H[0] = pack_f16x2(v0.x, v0.y); H[1] = pack_f16x2(v0.z, v0.w);         \
        H[2] = pack_f16x2(v1.x, v1.y); H[3] = pack_f16x2(v1.z, v1.w);         \
        H[4] = pack_f16x2(v2.x, v2.y); H[5] = pack_f16x2(v2.z, v2.w);         \
        H[6] = pack_f16x2(v3.x, v3.y); H[7] = pack_f16x2(v3.z, v3.w);         \
        uint16_t* dh = sm + (buf) * BUFE + dstA;                              \
        *(uint4*)(dh)     = *(uint4*)&H[0];                                   \
        *(uint4*)(dh + 8) = *(uint4*)&H[4];                                   \
    } while (0)

    // prologue: chunk 0 into buffer 0
    COPY_AB(0, 0);
    CP_WAIT0();
    CONV_A(0);
    __syncthreads();

    for (int c = 0; c < 16; ++c) {
        const int cur = c & 1, nxt = cur ^ 1;
        if (c < 15) COPY_AB(c + 1, nxt);

        // ---- MMA on buffer cur ----
        const uint16_t* base = sm + cur * BUFE;
#pragma unroll
        for (int ks = 0; ks < 2; ++ks) {
            const int kk = ks * 16;
            uint32_t a[2][4];
#pragma unroll
            for (int mt = 0; mt < 2; ++mt) {
                int r = wm + mt * 16 + (lane >> 2);
                int cc = kk + (lane & 3) * 2;
                a[mt][0] = *(const uint32_t*)(base + SA + r * LDA + cc);
                a[mt][1] = *(const uint32_t*)(base + SA + (r + 8) * LDA + cc);
                a[mt][2] = *(const uint32_t*)(base + SA + r * LDA + cc + 8);
                a[mt][3] = *(const uint32_t*)(base + SA + (r + 8) * LDA + cc + 8);
            }
#pragma unroll
            for (int nt = 0; nt < 8; ++nt) {
                int n = wn + nt * 8 + (lane >> 2);
                int kq = kk + (lane & 3) * 2;
                uint32_t bh0 = *(const uint32_t*)(base + SBH + n * LDA + kq);
                uint32_t bh1 = *(const uint32_t*)(base + SBH + n * LDA + kq + 8);
                uint32_t bl0 = *(const uint32_t*)(base + SBL + n * LDA + kq);
                uint32_t bl1 = *(const uint32_t*)(base + SBL + n * LDA + kq + 8);
#pragma unroll
                for (int mt = 0; mt < 2; ++mt) {
                    mma_f16(acc[mt][nt], a[mt], bh0, bh1);
                    mma_f16(acc[mt][nt], a[mt], bl0, bl1);
                }
            }
        }

        if (c < 15) { CP_WAIT0(); CONV_A(nxt); }
        __syncthreads();
    }

    // epilogue
#pragma unroll
    for (int mt = 0; mt < 2; ++mt) {
        int r0 = m0 + wm + mt * 16 + (lane >> 2);
        int r1 = r0 + 8;
#pragma unroll
        for (int nt = 0; nt < 8; ++nt) {
            int cc = wn + nt * 8 + (lane & 3) * 2;
            if (r0 < N_NODES)
                *(float2*)(out + (size_t)r0 * NHID + cc) = make_float2(acc[mt][nt][0], acc[mt][nt][1]);
            if (r1 < N_NODES)
                *(float2*)(out + (size_t)r1 * NHID + cc) = make_float2(acc[mt][nt][2], acc[mt][nt][3]);
        }
    }
}

// ---------------------------------------------------------------------------
// SpMM: warp per row, row_ptr, 4-edge unroll.
// ---------------------------------------------------------------------------
template <bool RELU>
__global__ __launch_bounds__(256) void spmm_kernel(const int* __restrict__ cols,
                                                   const float* __restrict__ vals,
                                                   const float* __restrict__ hin,
                                                   const float* __restrict__ bias,
                                                   float* __restrict__ hout)
{
    const int gw   = (blockIdx.x * blockDim.x + threadIdx.x) >> 5;
    const int lane = threadIdx.x & 31;
    if (gw >= N_NODES) return;

    const int start = g_rowptr[gw];
    const int end   = g_rowptr[gw + 1];

    float ax = 0.f, ay = 0.f, az = 0.f, aw = 0.f;
    int e = start;
    for (; e + 4 <= end; e += 4) {
        int   c0 = cols[e],     c1 = cols[e + 1], c2 = cols[e + 2], c3 = cols[e + 3];
        float v0 = vals[e],     v1 = vals[e + 1], v2 = vals[e + 2], v3 = vals[e + 3];
        float4 h0 = *(const float4*)(hin + (size_t)c0 * NHID + lane * 4);
        float4 h1 = *(const float4*)(hin + (size_t)c1 * NHID + lane * 4);
        float4 h2 = *(const float4*)(hin + (size_t)c2 * NHID + lane * 4);
        float4 h3 = *(const float4*)(hin + (size_t)c3 * NHID + lane * 4);
        ax = fmaf(v0, h0.x, ax); ay = fmaf(v0, h0.y, ay);
        az = fmaf(v0, h0.z, az); aw = fmaf(v0, h0.w, aw);
        ax = fmaf(v1, h1.x, ax); ay = fmaf(v1, h1.y, ay);
        az = fmaf(v1, h1.z, az); aw = fmaf(v1, h1.w, aw);
        ax = fmaf(v2, h2.x, ax); ay = fmaf(v2, h2.y, ay);
        az = fmaf(v2, h2.z, az); aw = fmaf(v2, h2.w, aw);
        ax = fmaf(v3, h3.x, ax); ay = fmaf(v3, h3.y, ay);
        az = fmaf(v3, h3.z, az); aw = fmaf(v3, h3.w, aw);
    }
    for (; e < end; ++e) {
        int   c0 = cols[e];
        float v0 = vals[e];
        float4 h0 = *(const float4*)(hin + (size_t)c0 * NHID + lane * 4);
        ax = fmaf(v0, h0.x, ax); ay = fmaf(v0, h0.y, ay);
        az = fmaf(v0, h0.z, az); aw = fmaf(v0, h0.w, aw);
    }
    if (RELU) {
        float4 b = ((const float4*)bias)[lane];
        ax = fmaxf(ax + b.x, 0.f); ay = fmaxf(ay + b.y, 0.f);
        az = fmaxf(az + b.z, 0.f); aw = fmaxf(aw + b.w, 0.f);
    }
    *(float4*)(hout + (size_t)gw * NHID + lane * 4) = make_float4(ax, ay, az, aw);
}

// ---------------------------------------------------------------------------
// GEMM2 via mma.sync bf16 split + fused bias + log_softmax. (kept)
// ---------------------------------------------------------------------------
#define LDH 136
#define G2_SHH 0
#define G2_SHL 8704
#define G2_SWH 17408
#define G2_SWL 26112
#define SMEM_G2_BYTES (34816 * 2)

__global__ __launch_bounds__(128) void gemm2_mma_kernel(const float* __restrict__ h,
                                                        const float* __restrict__ b2,
                                                        float* __restrict__ out)
{
    extern __shared__ uint16_t s2[];

    const int tid  = threadIdx.x;
    const int lane = tid & 31;
    const int wid  = tid >> 5;
    const int r0   = blockIdx.x * 64;

    const int row = tid >> 1, half = tid & 1;
    int rg = r0 + row;
    if (rg >= N_NODES) rg = N_NODES - 1;
    const float* hrow = h + (size_t)rg * NHID + half * 64;
#pragma unroll
    for (int g = 0; g < 2; ++g) {
        uint32_t H[16], L[16];
#pragma unroll
        for (int j = 0; j < 8; ++j) {
            float4 v = *(const float4*)(hrow + g * 32 + j * 4);
            uint32_t p0 = pack_bf16x2(v.x, v.y);
            uint32_t p1 = pack_bf16x2(v.z, v.w);
            H[2 * j]     = p0;
            H[2 * j + 1] = p1;
            L[2 * j]     = pack_bf16x2(v.x - bf_lo_f32(p0), v.y - bf_hi_f32(p0));
            L[2 * j + 1] = pack_bf16x2(v.z - bf_lo_f32(p1), v.w - bf_hi_f32(p1));
        }
        uint16_t* dh = s2 + G2_SHH + row * LDH + half * 64 + g * 32;
        uint16_t* dl = s2 + G2_SHL + row * LDH + half * 64 + g * 32;
#pragma unroll
        for (int j = 0; j < 4; ++j) {
            *(uint4*)(dh + j * 8) = *(uint4*)&H[j * 4];
            *(uint4*)(dl + j * 8) = *(uint4*)&L[j * 4];
        }
    }

    {
        const int n = tid >> 1;
        const uint16_t* wh = g_w2t_hi + n * NHID + half * 64;
        const uint16_t* wl = g_w2t_lo + n * NHID + half * 64;
        uint16_t* dh = s2 + G2_SWH + n * LDH + half * 64;
        uint16_t* dl = s2 + G2_SWL + n * LDH + half * 64;
#pragma unroll
        for (int j = 0; j < 8; ++j) {
            *(uint4*)(dh + j * 8) = *(const uint4*)(wh + j * 8);
            *(uint4*)(dl + j * 8) = *(const uint4*)(wl + j * 8);
        }
    }
    __syncthreads();

    float acc[8][4];
#pragma unroll
    for (int nt = 0; nt < 8; ++nt)
#pragma unroll
        for (int q = 0; q < 4; ++q) acc[nt][q] = 0.f;

    const int wr = wid * 16;
#pragma unroll
    for (int ks = 0; ks < 8; ++ks) {
        const int kk = ks * 16;
        const int r  = wr + (lane >> 2);
        const int cc = kk + (lane & 3) * 2;
        uint32_t a_hi[4], a_lo[4];
        a_hi[0] = *(const uint32_t*)(s2 + G2_SHH + r * LDH + cc);
        a_hi[1] = *(const uint32_t*)(s2 + G2_SHH + (r + 8) * LDH + cc);
        a_hi[2] = *(const uint32_t*)(s2 + G2_SHH + r * LDH + cc + 8);
        a_hi[3] = *(const uint32_t*)(s2 + G2_SHH + (r + 8) * LDH + cc + 8);
        a_lo[0] = *(const uint32_t*)(s2 + G2_SHL + r * LDH + cc);
        a_lo[1] = *(const uint32_t*)(s2 + G2_SHL + (r + 8) * LDH + cc);
        a_lo[2] = *(const uint32_t*)(s2 + G2_SHL + r * LDH + cc + 8);
        a_lo[3] = *(const uint32_t*)(s2 + G2_SHL + (r + 8) * LDH + cc + 8);
#pragma unroll
        for (int nt = 0; nt < 8; ++nt) {
            int n  = nt * 8 + (lane >> 2);
            int kq = kk + (lane & 3) * 2;
            uint32_t bh0 = *(const uint32_t*)(s2 + G2_SWH + n * LDH + kq);
            uint32_t bh1 = *(const uint32_t*)(s2 + G2_SWH + n * LDH + kq + 8);
            uint32_t bl0 = *(const uint32_t*)(s2 + G2_SWL + n * LDH + kq);
            uint32_t bl1 = *(const uint32_t*)(s2 + G2_SWL + n * LDH + kq + 8);
            mma_bf16(acc[nt], a_hi, bh0, bh1);
            mma_bf16(acc[nt], a_hi, bl0, bl1);
            mma_bf16(acc[nt], a_lo, bh0, bh1);
        }
    }

#pragma unroll
    for (int nt = 0; nt < 8; ++nt) {
        int c = nt * 8 + (lane & 3) * 2;
        float bb0 = b2[c], bb1 = b2[c + 1];
        acc[nt][0] += bb0; acc[nt][1] += bb1;
        acc[nt][2] += bb0; acc[nt][3] += bb1;
    }

    float m0 = -1e30f, m1 = -1e30f;
#pragma unroll
    for (int nt = 0; nt < 8; ++nt) {
        m0 = fmaxf(m0, fmaxf(acc[nt][0], acc[nt][1]));
        m1 = fmaxf(m1, fmaxf(acc[nt][2], acc[nt][3]));
    }
    m0 = fmaxf(m0, __shfl_xor_sync(0xffffffffu, m0, 1));
    m0 = fmaxf(m0, __shfl_xor_sync(0xffffffffu, m0, 2));
    m1 = fmaxf(m1, __shfl_xor_sync(0xffffffffu, m1, 1));
    m1 = fmaxf(m1, __shfl_xor_sync(0xffffffffu, m1, 2));

    float s0 = 0.f, s1 = 0.f;
#pragma unroll
    for (int nt = 0; nt < 8; ++nt) {
        s0 += expf(acc[nt][0] - m0) + expf(acc[nt][1] - m0);
        s1 += expf(acc[nt][2] - m1) + expf(acc[nt][3] - m1);
    }
    s0 += __shfl_xor_sync(0xffffffffu, s0, 1);
    s0 += __shfl_xor_sync(0xffffffffu, s0, 2);
    s1 += __shfl_xor_sync(0xffffffffu, s1, 1);
    s1 += __shfl_xor_sync(0xffffffffu, s1, 2);
    const float lse0 = m0 + logf(s0);
    const float lse1 = m1 + logf(s1);

    const int row0 = r0 + wr + (lane >> 2);
    const int row1 = row0 + 8;
#pragma unroll
    for (int nt = 0; nt < 8; ++nt) {
        int c = nt * 8 + (lane & 3) * 2;
        if (row0 < N_NODES)
            *(float2*)(out + (size_t)row0 * NCLASS + c) =
                make_float2(acc[nt][0] - lse0, acc[nt][1] - lse0);
        if (row1 < N_NODES)
            *(float2*)(out + (size_t)row1 * NCLASS + c) =
                make_float2(acc[nt][2] - lse1, acc[nt][3] - lse1);
    }
}

// ---------------------------------------------------------------------------
extern "C" void kernel_launch(void* const* d_in, const int* in_sizes, int n_in,
                              void* d_out, int out_size)
{
    const float* x    = (const float*)d_in[0];
    const int*   rows = (const int*)  d_in[1];
    const int*   cols = (const int*)  d_in[2];
    const float* vals = (const float*)d_in[3];
    const float* W1   = (const float*)d_in[4];
    const float* b1   = (const float*)d_in[5];
    const float* W2   = (const float*)d_in[6];
    const float* b2   = (const float*)d_in[7];
    float* out = (float*)d_out;

    float *h0, *h1;
    cudaGetSymbolAddress((void**)&h0, g_h0);
    cudaGetSymbolAddress((void**)&h1, g_h1);

    cudaFuncSetAttribute(gemm1_mma_kernel, cudaFuncAttributeMaxDynamicSharedMemorySize, SMEM_G1_BYTES);
    cudaFuncSetAttribute(gemm2_mma_kernel, cudaFuncAttributeMaxDynamicSharedMemorySize, SMEM_G2_BYTES);

    // 0) prep
    prep_w1_kernel<<<(NHID * NFEAT / 2 + 255) / 256, 256>>>(W1);
    prep_w2_kernel<<<(NCLASS * NHID / 2 + 255) / 256, 256>>>(W2);
    rowptr_kernel<<<(N_EDGES + 255) / 256, 256>>>(rows);

    // 1) h0 = X @ W1  (fp16 2-term, async A streaming)
    gemm1_mma_kernel<<<(N_NODES + 127) / 128, 256, SMEM_G1_BYTES>>>(x, h0);

    // 2) h1 = relu(A @ h0 + b1)
    const int spmm_blocks = (N_NODES * 32 + 255) / 256;
    spmm_kernel<true><<<spmm_blocks, 256>>>(cols, vals, h0, b1, h1);

    // 3) h0 <- A @ h1
    spmm_kernel<false><<<spmm_blocks, 256>>>(cols, vals, h1, b1, h0);

    // 4) out = logsoftmax(h0 @ W2 + b2)
    gemm2_mma_kernel<<<(N_NODES + 63) / 64, 128, SMEM_G2_BYTES>>>(h0, b2, out);
}

// round 10
// speedup vs baseline: 1.1810x; 1.0030x over previous
#include <cuda_runtime.h>
#include <math.h>
#include <stdint.h>

#define N_NODES 50000
#define N_EDGES 800000
#define NFEAT   512
#define NHID    128
#define NCLASS  64

// Scratch (allocation-free)
__device__ float g_h0[(size_t)N_NODES * NHID];
__device__ float g_h1[(size_t)N_NODES * NHID];
__device__ uint16_t g_w1t_hi[NHID * NFEAT];   // W1^T hi fp16 [n][k]
__device__ uint16_t g_w1t_lo[NHID * NFEAT];   // W1^T lo fp16 [n][k]
__device__ uint16_t g_w2t_hi[NCLASS * NHID];  // W2^T hi bf16 [n][k]
__device__ uint16_t g_w2t_lo[NCLASS * NHID];  // W2^T lo bf16 [n][k]
__device__ int g_rowptr[N_NODES + 1];

// ---------------------------------------------------------------------------
// helpers
// ---------------------------------------------------------------------------
__device__ __forceinline__ uint32_t smem_u32(const void* p) {
    uint32_t a;
    asm("{ .reg .u64 t; cvta.to.shared.u64 t, %1; cvt.u32.u64 %0, t; }" : "=r"(a) : "l"(p));
    return a;
}
__device__ __forceinline__ uint32_t pack_bf16x2(float lo, float hi) {
    uint32_t r;
    asm("cvt.rn.bf16x2.f32 %0, %1, %2;" : "=r"(r) : "f"(hi), "f"(lo));
    return r;
}
__device__ __forceinline__ float bf_lo_f32(uint32_t p) { return __uint_as_float(p << 16); }
__device__ __forceinline__ float bf_hi_f32(uint32_t p) { return __uint_as_float(p & 0xFFFF0000u); }
__device__ __forceinline__ uint32_t pack_f16x2(float lo, float hi) {
    uint32_t r;
    asm("cvt.rn.f16x2.f32 %0, %1, %2;" : "=r"(r) : "f"(hi), "f"(lo));
    return r;
}
__device__ __forceinline__ float f16_lo_f32(uint32_t p) {
    float f; asm("{ .reg .f16 h; mov.b32 {h, _}, %1; cvt.f32.f16 %0, h; }" : "=f"(f) : "r"(p));
    return f;
}
__device__ __forceinline__ float f16_hi_f32(uint32_t p) {
    float f; asm("{ .reg .f16 h; mov.b32 {_, h}, %1; cvt.f32.f16 %0, h; }" : "=f"(f) : "r"(p));
    return f;
}

__device__ __forceinline__ void mma_bf16(float* d, const uint32_t* a,
                                         uint32_t b0, uint32_t b1) {
    asm("mma.sync.aligned.m16n8k16.row.col.f32.bf16.bf16.f32 "
        "{%0,%1,%2,%3}, {%4,%5,%6,%7}, {%8,%9}, {%0,%1,%2,%3};"
        : "+f"(d[0]), "+f"(d[1]), "+f"(d[2]), "+f"(d[3])
        : "r"(a[0]), "r"(a[1]), "r"(a[2]), "r"(a[3]), "r"(b0), "r"(b1));
}
__device__ __forceinline__ void mma_f16(float* d, const uint32_t* a,
                                        uint32_t b0, uint32_t b1) {
    asm("mma.sync.aligned.m16n8k16.row.col.f32.f16.f16.f32 "
        "{%0,%1,%2,%3}, {%4,%5,%6,%7}, {%8,%9}, {%0,%1,%2,%3};"
        : "+f"(d[0]), "+f"(d[1]), "+f"(d[2]), "+f"(d[3])
        : "r"(a[0]), "r"(a[1]), "r"(a[2]), "r"(a[3]), "r"(b0), "r"(b1));
}
__device__ __forceinline__ void cp_async16(uint32_t dst, const void* src) {
    asm volatile("cp.async.cg.shared.global [%0], [%1], 16;" :: "r"(dst), "l"(src));
}
#define CP_COMMIT() asm volatile("cp.async.commit_group;" ::: "memory")
#define CP_WAIT0()  asm volatile("cp.async.wait_group 0;" ::: "memory")
#define CP_WAIT2()  asm volatile("cp.async.wait_group 2;" ::: "memory")
#define CP_WAIT3()  asm volatile("cp.async.wait_group 3;" ::: "memory")

// ---------------------------------------------------------------------------
// prep kernels
// ---------------------------------------------------------------------------
__global__ void prep_w1_kernel(const float* __restrict__ W1) {
    int idx = blockIdx.x * 256 + threadIdx.x;
    if (idx >= NHID * NFEAT / 2) return;
    int n = idx >> 8;
    int k2 = (idx & 255) * 2;
    float w0 = W1[(size_t)k2 * NHID + n];
    float w1 = W1[(size_t)(k2 + 1) * NHID + n];
    uint32_t ph = pack_f16x2(w0, w1);
    uint32_t pl = pack_f16x2(w0 - f16_lo_f32(ph), w1 - f16_hi_f32(ph));
    *(uint32_t*)&g_w1t_hi[n * NFEAT + k2] = ph;
    *(uint32_t*)&g_w1t_lo[n * NFEAT + k2] = pl;
}

__global__ void prep_w2_kernel(const float* __restrict__ W2) {
    int idx = blockIdx.x * 256 + threadIdx.x;
    if (idx >= NCLASS * NHID / 2) return;
    int n = idx >> 6;
    int k2 = (idx & 63) * 2;
    float w0 = W2[(size_t)k2 * NCLASS + n];
    float w1 = W2[(size_t)(k2 + 1) * NCLASS + n];
    uint32_t ph = pack_bf16x2(w0, w1);
    uint32_t pl = pack_bf16x2(w0 - bf_lo_f32(ph), w1 - bf_hi_f32(ph));
    *(uint32_t*)&g_w2t_hi[n * NHID + k2] = ph;
    *(uint32_t*)&g_w2t_lo[n * NHID + k2] = pl;
}

__global__ void rowptr_kernel(const int* __restrict__ rows) {
    int e = blockIdx.x * 256 + threadIdx.x;
    if (e >= N_EDGES) return;
    int r = rows[e];
    int rp = (e == 0) ? -1 : rows[e - 1];
    for (int q = rp + 1; q <= r; ++q) g_rowptr[q] = e;
    if (e == N_EDGES - 1)
        for (int q = r + 1; q <= N_NODES; ++q) g_rowptr[q] = N_EDGES;
}

// ---------------------------------------------------------------------------
// GEMM1: fp16 2-term, depth-2 async pipeline.
// CTA 128x128, 256 threads, 8 warps (4M x 2N), warp tile 32x64, BK=32.
// A: fp32 cp.async into 3-stage ring (pitch 36), converted to ONE fp16 buf
//    right before its MMA. B: fp16 hi/lo, double-buffered cp.async.
// Group ledger (iter c): issue A(c+2); wait_group 3 -> drains exactly
// A(c),B(c); conv; sync; MMA; sync; issue B(c+2) into freed buffer.
// SMEM: A_f16 10240 + B 2x20480 + A_stag 3x18432 = 106496 B -> 2 CTAs/SM.
// ---------------------------------------------------------------------------
#define LDA   40                 // fp16 pitch (elems)
#define AF16  0                  // A fp16 buffer (5120 elems)
#define BBUF(b) (5120 + (b) * 10240)   // hi at +0, lo at +5120 (elems)
#define FP16_ELEMS 25600
#define LDAF  36                 // fp32 staging pitch (floats)
#define STAGF 4608               // floats per staging buffer (128*36)
#define SMEM_G1_BYTES (FP16_ELEMS * 2 + 3 * STAGF * 4)   // 106496

__global__ __launch_bounds__(256, 2) void gemm1_mma_kernel(const float* __restrict__ x,
                                                           float* __restrict__ out)
{
    extern __shared__ uint16_t sm[];
    float* stag = (float*)(sm + FP16_ELEMS);
    const uint32_t smb = smem_u32(sm);
    const uint32_t stb = smem_u32(stag);

    const int tid  = threadIdx.x;
    const int wid  = tid >> 5;
    const int lane = tid & 31;
    const int m0   = blockIdx.x * 128;
    const int wm = (wid >> 1) * 32;   // 0,32,64,96
    const int wn = (wid & 1) * 64;    // 0,64

    float acc[2][8][4];
#pragma unroll
    for (int i = 0; i < 2; i++)
#pragma unroll
        for (int j = 0; j < 8; j++)
#pragma unroll
            for (int q = 0; q < 4; q++) acc[i][j][q] = 0.f;

    const int arow  = tid >> 1;       // 0..127
    const int ahalf = tid & 1;        // 0/1
    int rg = m0 + arow;
    if (rg >= N_NODES) rg = N_NODES - 1;
    const float* xrow = x + (size_t)rg * NFEAT + ahalf * 16;
    const uint16_t* bhrow = g_w1t_hi + (size_t)arow * NFEAT + ahalf * 16;
    const uint16_t* blrow = g_w1t_lo + (size_t)arow * NFEAT + ahalf * 16;
    const int stA  = arow * LDAF + ahalf * 16;      // fp32 elems (within stage)
    const int dstA = AF16 + arow * LDA + ahalf * 16; // fp16 elems
    const int dstB = arow * LDA + ahalf * 16;        // fp16 elems (n-row = arow)

#define COPY_A(c, st) do {                                                    \
        uint32_t da = stb + ((st) * STAGF + stA) * 4;                         \
        _Pragma("unroll")                                                     \
        for (int j = 0; j < 4; ++j)                                           \
            cp_async16(da + j * 16, xrow + (c) * 32 + j * 4);                 \
        CP_COMMIT();                                                          \
    } while (0)

#define COPY_B(c, buf) do {                                                   \
        uint32_t dh = smb + (BBUF(buf) + dstB) * 2;                           \
        uint32_t dl = dh + 5120 * 2;                                          \
        _Pragma("unroll")                                                     \
        for (int j = 0; j < 2; ++j) {                                         \
            cp_async16(dh + j * 16, bhrow + (c) * 32 + j * 8);                \
            cp_async16(dl + j * 16, blrow + (c) * 32 + j * 8);                \
        }                                                                     \
        CP_COMMIT();                                                          \
    } while (0)

#define CONV_A(st) do {                                                       \
        const float* sf = stag + (st) * STAGF + stA;                          \
        float4 v0 = *(const float4*)(sf);                                     \
        float4 v1 = *(const float4*)(sf + 4);                                 \
        float4 v2 = *(const float4*)(sf + 8);                                 \
        float4 v3 = *(const float4*)(sf + 12);                                \
        uint32_t H[8];                                                        \
        H[0] = pack_f16x2(v0.x, v0.y); H[1] = pack_f16x2(v0.z, v0.w);         \
        H[2] = pack_f16x2(v1.x, v1.y); H[3] = pack_f16x2(v1.z, v1.w);         \
        H[4] = pack_f16x2(v2.x, v2.y); H[5] = pack_f16x2(v2.z, v2.w);         \
        H[6] = pack_f16x2(v3.x, v3.y); H[7] = pack_f16x2(v3.z, v3.w);         \
        uint16_t* dh = sm + dstA;                                             \
        *(uint4*)(dh)     = *(uint4*)&H[0];                                   \
        *(uint4*)(dh + 8) = *(uint4*)&H[4];                                   \
    } while (0)

    // prologue: chunks 0 and 1 in flight (A and B as separate groups)
    COPY_A(0, 0);
    COPY_B(0, 0);
    COPY_A(1, 1);
    COPY_B(1, 1);

#pragma unroll 1
    for (int c = 0; c < 16; ++c) {
        if (c < 14) COPY_A(c + 2, (c + 2) % 3);

        // drain exactly the groups for chunk c
        if (c < 14)       CP_WAIT3();
        else if (c == 14) CP_WAIT2();
        else              CP_WAIT0();

        CONV_A(c % 3);
        __syncthreads();

        // ---- MMA on A fp16 buf + B buffer c&1 ----
        const uint16_t* baseB = sm + BBUF(c & 1);
#pragma unroll
        for (int ks = 0; ks < 2; ++ks) {
            const int kk = ks * 16;
            uint32_t a[2][4];
#pragma unroll
            for (int mt = 0; mt < 2; ++mt) {
                int r = wm + mt * 16 + (lane >> 2);
                int cc = kk + (lane & 3) * 2;
                a[mt][0] = *(const uint32_t*)(sm + AF16 + r * LDA + cc);
                a[mt][1] = *(const uint32_t*)(sm + AF16 + (r + 8) * LDA + cc);
                a[mt][2] = *(const uint32_t*)(sm + AF16 + r * LDA + cc + 8);
                a[mt][3] = *(const uint32_t*)(sm + AF16 + (r + 8) * LDA + cc + 8);
            }
#pragma unroll
            for (int nt = 0; nt < 8; ++nt) {
                int n = wn + nt * 8 + (lane >> 2);
                int kq = kk + (lane & 3) * 2;
                uint32_t bh0 = *(const uint32_t*)(baseB + n * LDA + kq);
                uint32_t bh1 = *(const uint32_t*)(baseB + n * LDA + kq + 8);
                uint32_t bl0 = *(const uint32_t*)(baseB + 5120 + n * LDA + kq);
                uint32_t bl1 = *(const uint32_t*)(baseB + 5120 + n * LDA + kq + 8);
#pragma unroll
                for (int mt = 0; mt < 2; ++mt) {
                    mma_f16(acc[mt][nt], a[mt], bh0, bh1);
                    mma_f16(acc[mt][nt], a[mt], bl0, bl1);
                }
            }
        }
        __syncthreads();

        if (c < 14) COPY_B(c + 2, c & 1);   // buffer MMA(c) just released
    }

    // epilogue
#pragma unroll
    for (int mt = 0; mt < 2; ++mt) {
        int r0 = m0 + wm + mt * 16 + (lane >> 2);
        int r1 = r0 + 8;
#pragma unroll
        for (int nt = 0; nt < 8; ++nt) {
            int cc = wn + nt * 8 + (lane & 3) * 2;
            if (r0 < N_NODES)
                *(float2*)(out + (size_t)r0 * NHID + cc) = make_float2(acc[mt][nt][0], acc[mt][nt][1]);
            if (r1 < N_NODES)
                *(float2*)(out + (size_t)r1 * NHID + cc) = make_float2(acc[mt][nt][2], acc[mt][nt][3]);
        }
    }
}

// ---------------------------------------------------------------------------
// SpMM: warp per row, row_ptr, 4-edge unroll.
// ---------------------------------------------------------------------------
template <bool RELU>
__global__ __launch_bounds__(256) void spmm_kernel(const int* __restrict__ cols,
                                                   const float* __restrict__ vals,
                                                   const float* __restrict__ hin,
                                                   const float* __restrict__ bias,
                                                   float* __restrict__ hout)
{
    const int gw   = (blockIdx.x * blockDim.x + threadIdx.x) >> 5;
    const int lane = threadIdx.x & 31;
    if (gw >= N_NODES) return;

    const int start = g_rowptr[gw];
    const int end   = g_rowptr[gw + 1];

    float ax = 0.f, ay = 0.f, az = 0.f, aw = 0.f;
    int e = start;
    for (; e + 4 <= end; e += 4) {
        int   c0 = cols[e],     c1 = cols[e + 1], c2 = cols[e + 2], c3 = cols[e + 3];
        float v0 = vals[e],     v1 = vals[e + 1], v2 = vals[e + 2], v3 = vals[e + 3];
        float4 h0 = *(const float4*)(hin + (size_t)c0 * NHID + lane * 4);
        float4 h1 = *(const float4*)(hin + (size_t)c1 * NHID + lane * 4);
        float4 h2 = *(const float4*)(hin + (size_t)c2 * NHID + lane * 4);
        float4 h3 = *(const float4*)(hin + (size_t)c3 * NHID + lane * 4);
        ax = fmaf(v0, h0.x, ax); ay = fmaf(v0, h0.y, ay);
        az = fmaf(v0, h0.z, az); aw = fmaf(v0, h0.w, aw);
        ax = fmaf(v1, h1.x, ax); ay = fmaf(v1, h1.y, ay);
        az = fmaf(v1, h1.z, az); aw = fmaf(v1, h1.w, aw);
        ax = fmaf(v2, h2.x, ax); ay = fmaf(v2, h2.y, ay);
        az = fmaf(v2, h2.z, az); aw = fmaf(v2, h2.w, aw);
        ax = fmaf(v3, h3.x, ax); ay = fmaf(v3, h3.y, ay);
        az = fmaf(v3, h3.z, az); aw = fmaf(v3, h3.w, aw);
    }
    for (; e < end; ++e) {
        int   c0 = cols[e];
        float v0 = vals[e];
        float4 h0 = *(const float4*)(hin + (size_t)c0 * NHID + lane * 4);
        ax = fmaf(v0, h0.x, ax); ay = fmaf(v0, h0.y, ay);
        az = fmaf(v0, h0.z, az); aw = fmaf(v0, h0.w, aw);
    }
    if (RELU) {
        float4 b = ((const float4*)bias)[lane];
        ax = fmaxf(ax + b.x, 0.f); ay = fmaxf(ay + b.y, 0.f);
        az = fmaxf(az + b.z, 0.f); aw = fmaxf(aw + b.w, 0.f);
    }
    *(float4*)(hout + (size_t)gw * NHID + lane * 4) = make_float4(ax, ay, az, aw);
}

// ---------------------------------------------------------------------------
// GEMM2 via mma.sync bf16 split + fused bias + log_softmax. (kept)
// ---------------------------------------------------------------------------
#define LDH 136
#define G2_SHH 0
#define G2_SHL 8704
#define G2_SWH 17408
#define G2_SWL 26112
#define SMEM_G2_BYTES (34816 * 2)

__global__ __launch_bounds__(128) void gemm2_mma_kernel(const float* __restrict__ h,
                                                        const float* __restrict__ b2,
                                                        float* __restrict__ out)
{
    extern __shared__ uint16_t s2[];

    const int tid  = threadIdx.x;
    const int lane = tid & 31;
    const int wid  = tid >> 5;
    const int r0   = blockIdx.x * 64;

    const int row = tid >> 1, half = tid & 1;
    int rg = r0 + row;
    if (rg >= N_NODES) rg = N_NODES - 1;
    const float* hrow = h + (size_t)rg * NHID + half * 64;
#pragma unroll
    for (int g = 0; g < 2; ++g) {
        uint32_t H[16], L[16];
#pragma unroll
        for (int j = 0; j < 8; ++j) {
            float4 v = *(const float4*)(hrow + g * 32 + j * 4);
            uint32_t p0 = pack_bf16x2(v.x, v.y);
            uint32_t p1 = pack_bf16x2(v.z, v.w);
            H[2 * j]     = p0;
            H[2 * j + 1] = p1;
            L[2 * j]     = pack_bf16x2(v.x - bf_lo_f32(p0), v.y - bf_hi_f32(p0));
            L[2 * j + 1] = pack_bf16x2(v.z - bf_lo_f32(p1), v.w - bf_hi_f32(p1));
        }
        uint16_t* dh = s2 + G2_SHH + row * LDH + half * 64 + g * 32;
        uint16_t* dl = s2 + G2_SHL + row * LDH + half * 64 + g * 32;
#pragma unroll
        for (int j = 0; j < 4; ++j) {
            *(uint4*)(dh + j * 8) = *(uint4*)&H[j * 4];
            *(uint4*)(dl + j * 8) = *(uint4*)&L[j * 4];
        }
    }

    {
        const int n = tid >> 1;
        const uint16_t* wh = g_w2t_hi + n * NHID + half * 64;
        const uint16_t* wl = g_w2t_lo + n * NHID + half * 64;
        uint16_t* dh = s2 + G2_SWH + n * LDH + half * 64;
        uint16_t* dl = s2 + G2_SWL + n * LDH + half * 64;
#pragma unroll
        for (int j = 0; j < 8; ++j) {
            *(uint4*)(dh + j * 8) = *(const uint4*)(wh + j * 8);
            *(uint4*)(dl + j * 8) = *(const uint4*)(wl + j * 8);
        }
    }
    __syncthreads();

    float acc[8][4];
#pragma unroll
    for (int nt = 0; nt < 8; ++nt)
#pragma unroll
        for (int q = 0; q < 4; ++q) acc[nt][q] = 0.f;

    const int wr = wid * 16;
#pragma unroll
    for (int ks = 0; ks < 8; ++ks) {
        const int kk = ks * 16;
        const int r  = wr + (lane >> 2);
        const int cc = kk + (lane & 3) * 2;
        uint32_t a_hi[4], a_lo[4];
        a_hi[0] = *(const uint32_t*)(s2 + G2_SHH + r * LDH + cc);
        a_hi[1] = *(const uint32_t*)(s2 + G2_SHH + (r + 8) * LDH + cc);
        a_hi[2] = *(const uint32_t*)(s2 + G2_SHH + r * LDH + cc + 8);
        a_hi[3] = *(const uint32_t*)(s2 + G2_SHH + (r + 8) * LDH + cc + 8);
        a_lo[0] = *(const uint32_t*)(s2 + G2_SHL + r * LDH + cc);
        a_lo[1] = *(const uint32_t*)(s2 + G2_SHL + (r + 8) * LDH + cc);
        a_lo[2] = *(const uint32_t*)(s2 + G2_SHL + r * LDH + cc + 8);
        a_lo[3] = *(const uint32_t*)(s2 + G2_SHL + (r + 8) * LDH + cc + 8);
#pragma unroll
        for (int nt = 0; nt < 8; ++nt) {
            int n  = nt * 8 + (lane >> 2);
            int kq = kk + (lane & 3) * 2;
            uint32_t bh0 = *(const uint32_t*)(s2 + G2_SWH + n * LDH + kq);
            uint32_t bh1 = *(const uint32_t*)(s2 + G2_SWH + n * LDH + kq + 8);
            uint32_t bl0 = *(const uint32_t*)(s2 + G2_SWL + n * LDH + kq);
            uint32_t bl1 = *(const uint32_t*)(s2 + G2_SWL + n * LDH + kq + 8);
            mma_bf16(acc[nt], a_hi, bh0, bh1);
            mma_bf16(acc[nt], a_hi, bl0, bl1);
            mma_bf16(acc[nt], a_lo, bh0, bh1);
        }
    }

#pragma unroll
    for (int nt = 0; nt < 8; ++nt) {
        int c = nt * 8 + (lane & 3) * 2;
        float bb0 = b2[c], bb1 = b2[c + 1];
        acc[nt][0] += bb0; acc[nt][1] += bb1;
        acc[nt][2] += bb0; acc[nt][3] += bb1;
    }

    float m0 = -1e30f, m1 = -1e30f;
#pragma unroll
    for (int nt = 0; nt < 8; ++nt) {
        m0 = fmaxf(m0, fmaxf(acc[nt][0], acc[nt][1]));
        m1 = fmaxf(m1, fmaxf(acc[nt][2], acc[nt][3]));
    }
    m0 = fmaxf(m0, __shfl_xor_sync(0xffffffffu, m0, 1));
    m0 = fmaxf(m0, __shfl_xor_sync(0xffffffffu, m0, 2));
    m1 = fmaxf(m1, __shfl_xor_sync(0xffffffffu, m1, 1));
    m1 = fmaxf(m1, __shfl_xor_sync(0xffffffffu, m1, 2));

    float s0 = 0.f, s1 = 0.f;
#pragma unroll
    for (int nt = 0; nt < 8; ++nt) {
        s0 += expf(acc[nt][0] - m0) + expf(acc[nt][1] - m0);
        s1 += expf(acc[nt][2] - m1) + expf(acc[nt][3] - m1);
    }
    s0 += __shfl_xor_sync(0xffffffffu, s0, 1);
    s0 += __shfl_xor_sync(0xffffffffu, s0, 2);
    s1 += __shfl_xor_sync(0xffffffffu, s1, 1);
    s1 += __shfl_xor_sync(0xffffffffu, s1, 2);
    const float lse0 = m0 + logf(s0);
    const float lse1 = m1 + logf(s1);

    const int row0 = r0 + wr + (lane >> 2);
    const int row1 = row0 + 8;
#pragma unroll
    for (int nt = 0; nt < 8; ++nt) {
        int c = nt * 8 + (lane & 3) * 2;
        if (row0 < N_NODES)
            *(float2*)(out + (size_t)row0 * NCLASS + c) =
                make_float2(acc[nt][0] - lse0, acc[nt][1] - lse0);
        if (row1 < N_NODES)
            *(float2*)(out + (size_t)row1 * NCLASS + c) =
                make_float2(acc[nt][2] - lse1, acc[nt][3] - lse1);
    }
}

// ---------------------------------------------------------------------------
extern "C" void kernel_launch(void* const* d_in, const int* in_sizes, int n_in,
                              void* d_out, int out_size)
{
    const float* x    = (const float*)d_in[0];
    const int*   rows = (const int*)  d_in[1];
    const int*   cols = (const int*)  d_in[2];
    const float* vals = (const float*)d_in[3];
    const float* W1   = (const float*)d_in[4];
    const float* b1   = (const float*)d_in[5];
    const float* W2   = (const float*)d_in[6];
    const float* b2   = (const float*)d_in[7];
    float* out = (float*)d_out;

    float *h0, *h1;
    cudaGetSymbolAddress((void**)&h0, g_h0);
    cudaGetSymbolAddress((void**)&h1, g_h1);

    cudaFuncSetAttribute(gemm1_mma_kernel, cudaFuncAttributeMaxDynamicSharedMemorySize, SMEM_G1_BYTES);
    cudaFuncSetAttribute(gemm2_mma_kernel, cudaFuncAttributeMaxDynamicSharedMemorySize, SMEM_G2_BYTES);

    // 0) prep
    prep_w1_kernel<<<(NHID * NFEAT / 2 + 255) / 256, 256>>>(W1);
    prep_w2_kernel<<<(NCLASS * NHID / 2 + 255) / 256, 256>>>(W2);
    rowptr_kernel<<<(N_EDGES + 255) / 256, 256>>>(rows);

    // 1) h0 = X @ W1  (fp16 2-term, depth-2 async pipeline)
    gemm1_mma_kernel<<<(N_NODES + 127) / 128, 256, SMEM_G1_BYTES>>>(x, h0);

    // 2) h1 = relu(A @ h0 + b1)
    const int spmm_blocks = (N_NODES * 32 + 255) / 256;
    spmm_kernel<true><<<spmm_blocks, 256>>>(cols, vals, h0, b1, h1);

    // 3) h0 <- A @ h1
    spmm_kernel<false><<<spmm_blocks, 256>>>(cols, vals, h1, b1, h0);

    // 4) out = logsoftmax(h0 @ W2 + b2)
    gemm2_mma_kernel<<<(N_NODES + 63) / 64, 128, SMEM_G2_BYTES>>>(h0, b2, out);
}

// round 11
// speedup vs baseline: 1.1831x; 1.0018x over previous
#include <cuda_runtime.h>
#include <math.h>
#include <stdint.h>

#define N_NODES 50000
#define N_EDGES 800000
#define NFEAT   512
#define NHID    128
#define NCLASS  64

// Scratch (allocation-free)
__device__ float g_h0[(size_t)N_NODES * NHID];
__device__ float g_h1[(size_t)N_NODES * NHID];
__device__ uint16_t g_w1t_hi[NHID * NFEAT];   // W1^T hi fp16 [n][k]
__device__ uint16_t g_w1t_lo[NHID * NFEAT];   // W1^T lo fp16 [n][k]
__device__ uint16_t g_w2t_hi[NCLASS * NHID];  // W2^T hi bf16 [n][k]
__device__ uint16_t g_w2t_lo[NCLASS * NHID];  // W2^T lo bf16 [n][k]
__device__ int g_rowptr[N_NODES + 1];

// ---------------------------------------------------------------------------
// helpers
// ---------------------------------------------------------------------------
__device__ __forceinline__ uint32_t smem_u32(const void* p) {
    uint32_t a;
    asm("{ .reg .u64 t; cvta.to.shared.u64 t, %1; cvt.u32.u64 %0, t; }" : "=r"(a) : "l"(p));
    return a;
}
__device__ __forceinline__ uint32_t pack_bf16x2(float lo, float hi) {
    uint32_t r;
    asm("cvt.rn.bf16x2.f32 %0, %1, %2;" : "=r"(r) : "f"(hi), "f"(lo));
    return r;
}
__device__ __forceinline__ float bf_lo_f32(uint32_t p) { return __uint_as_float(p << 16); }
__device__ __forceinline__ float bf_hi_f32(uint32_t p) { return __uint_as_float(p & 0xFFFF0000u); }
__device__ __forceinline__ uint32_t pack_f16x2(float lo, float hi) {
    uint32_t r;
    asm("cvt.rn.f16x2.f32 %0, %1, %2;" : "=r"(r) : "f"(hi), "f"(lo));
    return r;
}
__device__ __forceinline__ float f16_lo_f32(uint32_t p) {
    float f; asm("{ .reg .f16 h; mov.b32 {h, _}, %1; cvt.f32.f16 %0, h; }" : "=f"(f) : "r"(p));
    return f;
}
__device__ __forceinline__ float f16_hi_f32(uint32_t p) {
    float f; asm("{ .reg .f16 h; mov.b32 {_, h}, %1; cvt.f32.f16 %0, h; }" : "=f"(f) : "r"(p));
    return f;
}

__device__ __forceinline__ void mma_bf16(float* d, const uint32_t* a,
                                         uint32_t b0, uint32_t b1) {
    asm("mma.sync.aligned.m16n8k16.row.col.f32.bf16.bf16.f32 "
        "{%0,%1,%2,%3}, {%4,%5,%6,%7}, {%8,%9}, {%0,%1,%2,%3};"
        : "+f"(d[0]), "+f"(d[1]), "+f"(d[2]), "+f"(d[3])
        : "r"(a[0]), "r"(a[1]), "r"(a[2]), "r"(a[3]), "r"(b0), "r"(b1));
}
__device__ __forceinline__ void mma_f16(float* d, const uint32_t* a,
                                        uint32_t b0, uint32_t b1) {
    asm("mma.sync.aligned.m16n8k16.row.col.f32.f16.f16.f32 "
        "{%0,%1,%2,%3}, {%4,%5,%6,%7}, {%8,%9}, {%0,%1,%2,%3};"
        : "+f"(d[0]), "+f"(d[1]), "+f"(d[2]), "+f"(d[3])
        : "r"(a[0]), "r"(a[1]), "r"(a[2]), "r"(a[3]), "r"(b0), "r"(b1));
}
#define LDSM4(r0, r1, r2, r3, addr) \
    asm volatile("ldmatrix.sync.aligned.m8n8.x4.shared.b16 {%0,%1,%2,%3}, [%4];" \
        : "=r"(r0), "=r"(r1), "=r"(r2), "=r"(r3) : "r"(addr))

__device__ __forceinline__ void cp_async16(uint32_t dst, const void* src) {
    asm volatile("cp.async.cg.shared.global [%0], [%1], 16;" :: "r"(dst), "l"(src));
}
#define CP_COMMIT() asm volatile("cp.async.commit_group;" ::: "memory")
#define CP_WAIT0()  asm volatile("cp.async.wait_group 0;" ::: "memory")
#define CP_WAIT2()  asm volatile("cp.async.wait_group 2;" ::: "memory")
#define CP_WAIT3()  asm volatile("cp.async.wait_group 3;" ::: "memory")

// ---------------------------------------------------------------------------
// prep kernels
// ---------------------------------------------------------------------------
__global__ void prep_w1_kernel(const float* __restrict__ W1) {
    int idx = blockIdx.x * 256 + threadIdx.x;
    if (idx >= NHID * NFEAT / 2) return;
    int n = idx >> 8;
    int k2 = (idx & 255) * 2;
    float w0 = W1[(size_t)k2 * NHID + n];
    float w1 = W1[(size_t)(k2 + 1) * NHID + n];
    uint32_t ph = pack_f16x2(w0, w1);
    uint32_t pl = pack_f16x2(w0 - f16_lo_f32(ph), w1 - f16_hi_f32(ph));
    *(uint32_t*)&g_w1t_hi[n * NFEAT + k2] = ph;
    *(uint32_t*)&g_w1t_lo[n * NFEAT + k2] = pl;
}

__global__ void prep_w2_kernel(const float* __restrict__ W2) {
    int idx = blockIdx.x * 256 + threadIdx.x;
    if (idx >= NCLASS * NHID / 2) return;
    int n = idx >> 6;
    int k2 = (idx & 63) * 2;
    float w0 = W2[(size_t)k2 * NCLASS + n];
    float w1 = W2[(size_t)(k2 + 1) * NCLASS + n];
    uint32_t ph = pack_bf16x2(w0, w1);
    uint32_t pl = pack_bf16x2(w0 - bf_lo_f32(ph), w1 - bf_hi_f32(ph));
    *(uint32_t*)&g_w2t_hi[n * NHID + k2] = ph;
    *(uint32_t*)&g_w2t_lo[n * NHID + k2] = pl;
}

__global__ void rowptr_kernel(const int* __restrict__ rows) {
    int e = blockIdx.x * 256 + threadIdx.x;
    if (e >= N_EDGES) return;
    int r = rows[e];
    int rp = (e == 0) ? -1 : rows[e - 1];
    for (int q = rp + 1; q <= r; ++q) g_rowptr[q] = e;
    if (e == N_EDGES - 1)
        for (int q = r + 1; q <= N_NODES; ++q) g_rowptr[q] = N_EDGES;
}

// ---------------------------------------------------------------------------
// GEMM1: fp16 2-term, depth-2 async pipeline, ldmatrix fragment loads.
// CTA 128x128, 256 threads, 8 warps (4M x 2N), warp tile 32x64, BK=32.
// ---------------------------------------------------------------------------
#define LDA   40                 // fp16 pitch (elems)
#define AF16  0                  // A fp16 buffer (5120 elems)
#define BBUF(b) (5120 + (b) * 10240)   // hi at +0, lo at +5120 (elems)
#define FP16_ELEMS 25600
#define LDAF  36                 // fp32 staging pitch (floats)
#define STAGF 4608               // floats per staging buffer (128*36)
#define SMEM_G1_BYTES (FP16_ELEMS * 2 + 3 * STAGF * 4)   // 106496

__global__ __launch_bounds__(256, 2) void gemm1_mma_kernel(const float* __restrict__ x,
                                                           float* __restrict__ out)
{
    extern __shared__ uint16_t sm[];
    float* stag = (float*)(sm + FP16_ELEMS);
    const uint32_t smb = smem_u32(sm);
    const uint32_t stb = smem_u32(stag);

    const int tid  = threadIdx.x;
    const int wid  = tid >> 5;
    const int lane = tid & 31;
    const int m0   = blockIdx.x * 128;
    const int wm = (wid >> 1) * 32;   // 0,32,64,96
    const int wn = (wid & 1) * 64;    // 0,64

    float acc[2][8][4];
#pragma unroll
    for (int i = 0; i < 2; i++)
#pragma unroll
        for (int j = 0; j < 8; j++)
#pragma unroll
            for (int q = 0; q < 4; q++) acc[i][j][q] = 0.f;

    const int arow  = tid >> 1;       // 0..127
    const int ahalf = tid & 1;        // 0/1
    int rg = m0 + arow;
    if (rg >= N_NODES) rg = N_NODES - 1;
    const float* xrow = x + (size_t)rg * NFEAT + ahalf * 16;
    const uint16_t* bhrow = g_w1t_hi + (size_t)arow * NFEAT + ahalf * 16;
    const uint16_t* blrow = g_w1t_lo + (size_t)arow * NFEAT + ahalf * 16;
    const int stA  = arow * LDAF + ahalf * 16;       // fp32 elems (within stage)
    const int dstA = AF16 + arow * LDA + ahalf * 16; // fp16 elems
    const int dstB = arow * LDA + ahalf * 16;        // fp16 elems (n-row = arow)

    // ldmatrix per-lane base addresses (bytes).
    // x4 quad layout: lanes {0-7,8-15,16-23,24-31} -> (row, row+8, row k+8, row+8 k+8)
    const int lrow = (lane & 7) + ((lane >> 3) & 1) * 8;
    const int lkof = (lane >> 4) * 8;
    // A: rows wm + mt*16 + lrow, k = kk + lkof
    const uint32_t aAddr0 = smb + (uint32_t)((AF16 + (wm + lrow) * LDA + lkof) * 2);
    // B: rows wn + ntp*16 + lrow, k = kk + lkof (region base added per buffer)
    const uint32_t bRel   = (uint32_t)(((wn + lrow) * LDA + lkof) * 2);

#define COPY_A(c, st) do {                                                    \
        uint32_t da = stb + ((st) * STAGF + stA) * 4;                         \
        _Pragma("unroll")                                                     \
        for (int j = 0; j < 4; ++j)                                           \
            cp_async16(da + j * 16, xrow + (c) * 32 + j * 4);                 \
        CP_COMMIT();                                                          \
    } while (0)

#define COPY_B(c, buf) do {                                                   \
        uint32_t dh = smb + (BBUF(buf) + dstB) * 2;                           \
        uint32_t dl = dh + 5120 * 2;                                          \
        _Pragma("unroll")                                                     \
        for (int j = 0; j < 2; ++j) {                                         \
            cp_async16(dh + j * 16, bhrow + (c) * 32 + j * 8);                \
            cp_async16(dl + j * 16, blrow + (c) * 32 + j * 8);                \
        }                                                                     \
        CP_COMMIT();                                                          \
    } while (0)

#define CONV_A(st) do {                                                       \
        const float* sf = stag + (st) * STAGF + stA;                          \
        float4 v0 = *(const float4*)(sf);                                     \
        float4 v1 = *(const float4*)(sf + 4);                                 \
        float4 v2 = *(const float4*)(sf + 8);                                 \
        float4 v3 = *(const float4*)(sf + 12);                                \
        uint32_t H[8];                                                        \
        H[0] = pack_f16x2(v0.x, v0.y); H[1] = pack_f16x2(v0.z, v0.w);         \
        H[2] = pack_f16x2(v1.x, v1.y); H[3] = pack_f16x2(v1.z, v1.w);         \
        H[4] = pack_f16x2(v2.x, v2.y); H[5] = pack_f16x2(v2.z, v2.w);         \
        H[6] = pack_f16x2(v3.x, v3.y); H[7] = pack_f16x2(v3.z, v3.w);         \
        uint16_t* dh = sm + dstA;                                             \
        *(uint4*)(dh)     = *(uint4*)&H[0];                                   \
        *(uint4*)(dh + 8) = *(uint4*)&H[4];                                   \
    } while (0)

    // prologue: chunks 0 and 1 in flight (A and B as separate groups)
    COPY_A(0, 0);
    COPY_B(0, 0);
    COPY_A(1, 1);
    COPY_B(1, 1);

#pragma unroll 1
    for (int c = 0; c < 16; ++c) {
        if (c < 14) COPY_A(c + 2, (c + 2) % 3);

        if (c < 14)       CP_WAIT3();
        else if (c == 14) CP_WAIT2();
        else              CP_WAIT0();

        CONV_A(c % 3);
        __syncthreads();

        // ---- MMA via ldmatrix on A fp16 buf + B buffer c&1 ----
        const uint32_t bHi = smb + (uint32_t)(BBUF(c & 1) * 2) + bRel;
        const uint32_t bLo = bHi + 5120 * 2;
#pragma unroll
        for (int ks = 0; ks < 2; ++ks) {
            const uint32_t kb = ks * 32;   // 16 elems * 2B
            uint32_t a0[4], a1[4];
            LDSM4(a0[0], a0[1], a0[2], a0[3], aAddr0 + kb);
            LDSM4(a1[0], a1[1], a1[2], a1[3], aAddr0 + 16 * LDA * 2 + kb);
#pragma unroll
            for (int ntp = 0; ntp < 4; ++ntp) {
                const uint32_t boff = (uint32_t)(ntp * 16 * LDA * 2) + kb;
                uint32_t bh[4], bl[4];
                LDSM4(bh[0], bh[1], bh[2], bh[3], bHi + boff);
                LDSM4(bl[0], bl[1], bl[2], bl[3], bLo + boff);
                float* c00 = acc[0][ntp * 2];
                float* c01 = acc[0][ntp * 2 + 1];
                float* c10 = acc[1][ntp * 2];
                float* c11 = acc[1][ntp * 2 + 1];
                mma_f16(c00, a0, bh[0], bh[2]);
                mma_f16(c01, a0, bh[1], bh[3]);
                mma_f16(c10, a1, bh[0], bh[2]);
                mma_f16(c11, a1, bh[1], bh[3]);
                mma_f16(c00, a0, bl[0], bl[2]);
                mma_f16(c01, a0, bl[1], bl[3]);
                mma_f16(c10, a1, bl[0], bl[2]);
                mma_f16(c11, a1, bl[1], bl[3]);
            }
        }
        __syncthreads();

        if (c < 14) COPY_B(c + 2, c & 1);   // buffer MMA(c) just released
    }

    // epilogue
#pragma unroll
    for (int mt = 0; mt < 2; ++mt) {
        int r0 = m0 + wm + mt * 16 + (lane >> 2);
        int r1 = r0 + 8;
#pragma unroll
        for (int nt = 0; nt < 8; ++nt) {
            int cc = wn + nt * 8 + (lane & 3) * 2;
            if (r0 < N_NODES)
                *(float2*)(out + (size_t)r0 * NHID + cc) = make_float2(acc[mt][nt][0], acc[mt][nt][1]);
            if (r1 < N_NODES)
                *(float2*)(out + (size_t)r1 * NHID + cc) = make_float2(acc[mt][nt][2], acc[mt][nt][3]);
        }
    }
}

// ---------------------------------------------------------------------------
// SpMM: warp per row, row_ptr, 4-edge unroll.
// ---------------------------------------------------------------------------
template <bool RELU>
__global__ __launch_bounds__(256) void spmm_kernel(const int* __restrict__ cols,
                                                   const float* __restrict__ vals,
                                                   const float* __restrict__ hin,
                                                   const float* __restrict__ bias,
                                                   float* __restrict__ hout)
{
    const int gw   = (blockIdx.x * blockDim.x + threadIdx.x) >> 5;
    const int lane = threadIdx.x & 31;
    if (gw >= N_NODES) return;

    const int start = g_rowptr[gw];
    const int end   = g_rowptr[gw + 1];

    float ax = 0.f, ay = 0.f, az = 0.f, aw = 0.f;
    int e = start;
    for (; e + 4 <= end; e += 4) {
        int   c0 = cols[e],     c1 = cols[e + 1], c2 = cols[e + 2], c3 = cols[e + 3];
        float v0 = vals[e],     v1 = vals[e + 1], v2 = vals[e + 2], v3 = vals[e + 3];
        float4 h0 = *(const float4*)(hin + (size_t)c0 * NHID + lane * 4);
        float4 h1 = *(const float4*)(hin + (size_t)c1 * NHID + lane * 4);
        float4 h2 = *(const float4*)(hin + (size_t)c2 * NHID + lane * 4);
        float4 h3 = *(const float4*)(hin + (size_t)c3 * NHID + lane * 4);
        ax = fmaf(v0, h0.x, ax); ay = fmaf(v0, h0.y, ay);
        az = fmaf(v0, h0.z, az); aw = fmaf(v0, h0.w, aw);
        ax = fmaf(v1, h1.x, ax); ay = fmaf(v1, h1.y, ay);
        az = fmaf(v1, h1.z, az); aw = fmaf(v1, h1.w, aw);
        ax = fmaf(v2, h2.x, ax); ay = fmaf(v2, h2.y, ay);
        az = fmaf(v2, h2.z, az); aw = fmaf(v2, h2.w, aw);
        ax = fmaf(v3, h3.x, ax); ay = fmaf(v3, h3.y, ay);
        az = fmaf(v3, h3.z, az); aw = fmaf(v3, h3.w, aw);
    }
    for (; e < end; ++e) {
        int   c0 = cols[e];
        float v0 = vals[e];
        float4 h0 = *(const float4*)(hin + (size_t)c0 * NHID + lane * 4);
        ax = fmaf(v0, h0.x, ax); ay = fmaf(v0, h0.y, ay);
        az = fmaf(v0, h0.z, az); aw = fmaf(v0, h0.w, aw);
    }
    if (RELU) {
        float4 b = ((const float4*)bias)[lane];
        ax = fmaxf(ax + b.x, 0.f); ay = fmaxf(ay + b.y, 0.f);
        az = fmaxf(az + b.z, 0.f); aw = fmaxf(aw + b.w, 0.f);
    }
    *(float4*)(hout + (size_t)gw * NHID + lane * 4) = make_float4(ax, ay, az, aw);
}

// ---------------------------------------------------------------------------
// GEMM2 via mma.sync bf16 split + fused bias + log_softmax. (kept)
// ---------------------------------------------------------------------------
#define LDH 136
#define G2_SHH 0
#define G2_SHL 8704
#define G2_SWH 17408
#define G2_SWL 26112
#define SMEM_G2_BYTES (34816 * 2)

__global__ __launch_bounds__(128) void gemm2_mma_kernel(const float* __restrict__ h,
                                                        const float* __restrict__ b2,
                                                        float* __restrict__ out)
{
    extern __shared__ uint16_t s2[];

    const int tid  = threadIdx.x;
    const int lane = tid & 31;
    const int wid  = tid >> 5;
    const int r0   = blockIdx.x * 64;

    const int row = tid >> 1, half = tid & 1;
    int rg = r0 + row;
    if (rg >= N_NODES) rg = N_NODES - 1;
    const float* hrow = h + (size_t)rg * NHID + half * 64;
#pragma unroll
    for (int g = 0; g < 2; ++g) {
        uint32_t H[16], L[16];
#pragma unroll
        for (int j = 0; j < 8; ++j) {
            float4 v = *(const float4*)(hrow + g * 32 + j * 4);
            uint32_t p0 = pack_bf16x2(v.x, v.y);
            uint32_t p1 = pack_bf16x2(v.z, v.w);
            H[2 * j]     = p0;
            H[2 * j + 1] = p1;
            L[2 * j]     = pack_bf16x2(v.x - bf_lo_f32(p0), v.y - bf_hi_f32(p0));
            L[2 * j + 1] = pack_bf16x2(v.z - bf_lo_f32(p1), v.w - bf_hi_f32(p1));
        }
        uint16_t* dh = s2 + G2_SHH + row * LDH + half * 64 + g * 32;
        uint16_t* dl = s2 + G2_SHL + row * LDH + half * 64 + g * 32;
#pragma unroll
        for (int j = 0; j < 4; ++j) {
            *(uint4*)(dh + j * 8) = *(uint4*)&H[j * 4];
            *(uint4*)(dl + j * 8) = *(uint4*)&L[j * 4];
        }
    }

    {
        const int n = tid >> 1;
        const uint16_t* wh = g_w2t_hi + n * NHID + half * 64;
        const uint16_t* wl = g_w2t_lo + n * NHID + half * 64;
        uint16_t* dh = s2 + G2_SWH + n * LDH + half * 64;
        uint16_t* dl = s2 + G2_SWL + n * LDH + half * 64;
#pragma unroll
        for (int j = 0; j < 8; ++j) {
            *(uint4*)(dh + j * 8) = *(const uint4*)(wh + j * 8);
            *(uint4*)(dl + j * 8) = *(const uint4*)(wl + j * 8);
        }
    }
    __syncthreads();

    float acc[8][4];
#pragma unroll
    for (int nt = 0; nt < 8; ++nt)
#pragma unroll
        for (int q = 0; q < 4; ++q) acc[nt][q] = 0.f;

    const int wr = wid * 16;
#pragma unroll
    for (int ks = 0; ks < 8; ++ks) {
        const int kk = ks * 16;
        const int r  = wr + (lane >> 2);
        const int cc = kk + (lane & 3) * 2;
        uint32_t a_hi[4], a_lo[4];
        a_hi[0] = *(const uint32_t*)(s2 + G2_SHH + r * LDH + cc);
        a_hi[1] = *(const uint32_t*)(s2 + G2_SHH + (r + 8) * LDH + cc);
        a_hi[2] = *(const uint32_t*)(s2 + G2_SHH + r * LDH + cc + 8);
        a_hi[3] = *(const uint32_t*)(s2 + G2_SHH + (r + 8) * LDH + cc + 8);
        a_lo[0] = *(const uint32_t*)(s2 + G2_SHL + r * LDH + cc);
        a_lo[1] = *(const uint32_t*)(s2 + G2_SHL + (r + 8) * LDH + cc);
        a_lo[2] = *(const uint32_t*)(s2 + G2_SHL + r * LDH + cc + 8);
        a_lo[3] = *(const uint32_t*)(s2 + G2_SHL + (r + 8) * LDH + cc + 8);
#pragma unroll
        for (int nt = 0; nt < 8; ++nt) {
            int n  = nt * 8 + (lane >> 2);
            int kq = kk + (lane & 3) * 2;
            uint32_t bh0 = *(const uint32_t*)(s2 + G2_SWH + n * LDH + kq);
            uint32_t bh1 = *(const uint32_t*)(s2 + G2_SWH + n * LDH + kq + 8);
            uint32_t bl0 = *(const uint32_t*)(s2 + G2_SWL + n * LDH + kq);
            uint32_t bl1 = *(const uint32_t*)(s2 + G2_SWL + n * LDH + kq + 8);
            mma_bf16(acc[nt], a_hi, bh0, bh1);
            mma_bf16(acc[nt], a_hi, bl0, bl1);
            mma_bf16(acc[nt], a_lo, bh0, bh1);
        }
    }

#pragma unroll
    for (int nt = 0; nt < 8; ++nt) {
        int c = nt * 8 + (lane & 3) * 2;
        float bb0 = b2[c], bb1 = b2[c + 1];
        acc[nt][0] += bb0; acc[nt][1] += bb1;
        acc[nt][2] += bb0; acc[nt][3] += bb1;
    }

    float m0 = -1e30f, m1 = -1e30f;
#pragma unroll
    for (int nt = 0; nt < 8; ++nt) {
        m0 = fmaxf(m0, fmaxf(acc[nt][0], acc[nt][1]));
        m1 = fmaxf(m1, fmaxf(acc[nt][2], acc[nt][3]));
    }
    m0 = fmaxf(m0, __shfl_xor_sync(0xffffffffu, m0, 1));
    m0 = fmaxf(m0, __shfl_xor_sync(0xffffffffu, m0, 2));
    m1 = fmaxf(m1, __shfl_xor_sync(0xffffffffu, m1, 1));
    m1 = fmaxf(m1, __shfl_xor_sync(0xffffffffu, m1, 2));

    float s0 = 0.f, s1 = 0.f;
#pragma unroll
    for (int nt = 0; nt < 8; ++nt) {
        s0 += expf(acc[nt][0] - m0) + expf(acc[nt][1] - m0);
        s1 += expf(acc[nt][2] - m1) + expf(acc[nt][3] - m1);
    }
    s0 += __shfl_xor_sync(0xffffffffu, s0, 1);
    s0 += __shfl_xor_sync(0xffffffffu, s0, 2);
    s1 += __shfl_xor_sync(0xffffffffu, s1, 1);
    s1 += __shfl_xor_sync(0xffffffffu, s1, 2);
    const float lse0 = m0 + logf(s0);
    const float lse1 = m1 + logf(s1);

    const int row0 = r0 + wr + (lane >> 2);
    const int row1 = row0 + 8;
#pragma unroll
    for (int nt = 0; nt < 8; ++nt) {
        int c = nt * 8 + (lane & 3) * 2;
        if (row0 < N_NODES)
            *(float2*)(out + (size_t)row0 * NCLASS + c) =
                make_float2(acc[nt][0] - lse0, acc[nt][1] - lse0);
        if (row1 < N_NODES)
            *(float2*)(out + (size_t)row1 * NCLASS + c) =
                make_float2(acc[nt][2] - lse1, acc[nt][3] - lse1);
    }
}

// ---------------------------------------------------------------------------
extern "C" void kernel_launch(void* const* d_in, const int* in_sizes, int n_in,
                              void* d_out, int out_size)
{
    const float* x    = (const float*)d_in[0];
    const int*   rows = (const int*)  d_in[1];
    const int*   cols = (const int*)  d_in[2];
    const float* vals = (const float*)d_in[3];
    const float* W1   = (const float*)d_in[4];
    const float* b1   = (const float*)d_in[5];
    const float* W2   = (const float*)d_in[6];
    const float* b2   = (const float*)d_in[7];
    float* out = (float*)d_out;

    float *h0, *h1;
    cudaGetSymbolAddress((void**)&h0, g_h0);
    cudaGetSymbolAddress((void**)&h1, g_h1);

    cudaFuncSetAttribute(gemm1_mma_kernel, cudaFuncAttributeMaxDynamicSharedMemorySize, SMEM_G1_BYTES);
    cudaFuncSetAttribute(gemm2_mma_kernel, cudaFuncAttributeMaxDynamicSharedMemorySize, SMEM_G2_BYTES);

    // 0) prep
    prep_w1_kernel<<<(NHID * NFEAT / 2 + 255) / 256, 256>>>(W1);
    prep_w2_kernel<<<(NCLASS * NHID / 2 + 255) / 256, 256>>>(W2);
    rowptr_kernel<<<(N_EDGES + 255) / 256, 256>>>(rows);

    // 1) h0 = X @ W1  (fp16 2-term, ldmatrix + async pipeline)
    gemm1_mma_kernel<<<(N_NODES + 127) / 128, 256, SMEM_G1_BYTES>>>(x, h0);

    // 2) h1 = relu(A @ h0 + b1)
    const int spmm_blocks = (N_NODES * 32 + 255) / 256;
    spmm_kernel<true><<<spmm_blocks, 256>>>(cols, vals, h0, b1, h1);

    // 3) h0 <- A @ h1
    spmm_kernel<false><<<spmm_blocks, 256>>>(cols, vals, h1, b1, h0);

    // 4) out = logsoftmax(h0 @ W2 + b2)
    gemm2_mma_kernel<<<(N_NODES + 63) / 64, 128, SMEM_G2_BYTES>>>(h0, b2, out);
}

// round 12
// speedup vs baseline: 1.3089x; 1.1063x over previous
#include <cuda_runtime.h>
#include <cuda_fp16.h>
#include <math.h>
#include <stdint.h>

#define N_NODES 50000
#define N_EDGES 800000
#define NFEAT   512
#define NHID    128
#define NCLASS  64

// Scratch (allocation-free) — h0/h1 now fp16
__device__ uint16_t g_h0[(size_t)N_NODES * NHID];
__device__ uint16_t g_h1[(size_t)N_NODES * NHID];
__device__ uint16_t g_w1t_hi[NHID * NFEAT];   // W1^T hi fp16 [n][k]
__device__ uint16_t g_w1t_lo[NHID * NFEAT];   // W1^T lo fp16 [n][k]
__device__ uint16_t g_w2t_hi[NCLASS * NHID];  // W2^T hi fp16 [n][k]
__device__ uint16_t g_w2t_lo[NCLASS * NHID];  // W2^T lo fp16 [n][k]
__device__ int g_rowptr[N_NODES + 1];

// ---------------------------------------------------------------------------
// helpers
// ---------------------------------------------------------------------------
__device__ __forceinline__ uint32_t smem_u32(const void* p) {
    uint32_t a;
    asm("{ .reg .u64 t; cvta.to.shared.u64 t, %1; cvt.u32.u64 %0, t; }" : "=r"(a) : "l"(p));
    return a;
}
__device__ __forceinline__ uint32_t pack_f16x2(float lo, float hi) {
    uint32_t r;
    asm("cvt.rn.f16x2.f32 %0, %1, %2;" : "=r"(r) : "f"(hi), "f"(lo));
    return r;
}
__device__ __forceinline__ float f16_lo_f32(uint32_t p) {
    float f; asm("{ .reg .f16 h; mov.b32 {h, _}, %1; cvt.f32.f16 %0, h; }" : "=f"(f) : "r"(p));
    return f;
}
__device__ __forceinline__ float f16_hi_f32(uint32_t p) {
    float f; asm("{ .reg .f16 h; mov.b32 {_, h}, %1; cvt.f32.f16 %0, h; }" : "=f"(f) : "r"(p));
    return f;
}

__device__ __forceinline__ void mma_f16(float* d, const uint32_t* a,
                                        uint32_t b0, uint32_t b1) {
    asm("mma.sync.aligned.m16n8k16.row.col.f32.f16.f16.f32 "
        "{%0,%1,%2,%3}, {%4,%5,%6,%7}, {%8,%9}, {%0,%1,%2,%3};"
        : "+f"(d[0]), "+f"(d[1]), "+f"(d[2]), "+f"(d[3])
        : "r"(a[0]), "r"(a[1]), "r"(a[2]), "r"(a[3]), "r"(b0), "r"(b1));
}
#define LDSM4(r0, r1, r2, r3, addr) \
    asm volatile("ldmatrix.sync.aligned.m8n8.x4.shared.b16 {%0,%1,%2,%3}, [%4];" \
        : "=r"(r0), "=r"(r1), "=r"(r2), "=r"(r3) : "r"(addr))

__device__ __forceinline__ void cp_async16(uint32_t dst, const void* src) {
    asm volatile("cp.async.cg.shared.global [%0], [%1], 16;" :: "r"(dst), "l"(src));
}
#define CP_COMMIT() asm volatile("cp.async.commit_group;" ::: "memory")
#define CP_WAIT0()  asm volatile("cp.async.wait_group 0;" ::: "memory")
#define CP_WAIT2()  asm volatile("cp.async.wait_group 2;" ::: "memory")
#define CP_WAIT3()  asm volatile("cp.async.wait_group 3;" ::: "memory")

// ---------------------------------------------------------------------------
// prep kernels
// ---------------------------------------------------------------------------
__global__ void prep_w1_kernel(const float* __restrict__ W1) {
    int idx = blockIdx.x * 256 + threadIdx.x;
    if (idx >= NHID * NFEAT / 2) return;
    int n = idx >> 8;
    int k2 = (idx & 255) * 2;
    float w0 = W1[(size_t)k2 * NHID + n];
    float w1 = W1[(size_t)(k2 + 1) * NHID + n];
    uint32_t ph = pack_f16x2(w0, w1);
    uint32_t pl = pack_f16x2(w0 - f16_lo_f32(ph), w1 - f16_hi_f32(ph));
    *(uint32_t*)&g_w1t_hi[n * NFEAT + k2] = ph;
    *(uint32_t*)&g_w1t_lo[n * NFEAT + k2] = pl;
}

__global__ void prep_w2_kernel(const float* __restrict__ W2) {
    int idx = blockIdx.x * 256 + threadIdx.x;
    if (idx >= NCLASS * NHID / 2) return;
    int n = idx >> 6;
    int k2 = (idx & 63) * 2;
    float w0 = W2[(size_t)k2 * NCLASS + n];
    float w1 = W2[(size_t)(k2 + 1) * NCLASS + n];
    uint32_t ph = pack_f16x2(w0, w1);
    uint32_t pl = pack_f16x2(w0 - f16_lo_f32(ph), w1 - f16_hi_f32(ph));
    *(uint32_t*)&g_w2t_hi[n * NHID + k2] = ph;
    *(uint32_t*)&g_w2t_lo[n * NHID + k2] = pl;
}

__global__ void rowptr_kernel(const int* __restrict__ rows) {
    int e = blockIdx.x * 256 + threadIdx.x;
    if (e >= N_EDGES) return;
    int r = rows[e];
    int rp = (e == 0) ? -1 : rows[e - 1];
    for (int q = rp + 1; q <= r; ++q) g_rowptr[q] = e;
    if (e == N_EDGES - 1)
        for (int q = r + 1; q <= N_NODES; ++q) g_rowptr[q] = N_EDGES;
}

// ---------------------------------------------------------------------------
// GEMM1: fp16 2-term, depth-2 async pipeline, ldmatrix (R11 mainloop),
// fp16 output.
// ---------------------------------------------------------------------------
#define LDA   40
#define AF16  0
#define BBUF(b) (5120 + (b) * 10240)
#define FP16_ELEMS 25600
#define LDAF  36
#define STAGF 4608
#define SMEM_G1_BYTES (FP16_ELEMS * 2 + 3 * STAGF * 4)   // 106496

__global__ __launch_bounds__(256, 2) void gemm1_mma_kernel(const float* __restrict__ x,
                                                           uint16_t* __restrict__ out)
{
    extern __shared__ uint16_t sm[];
    float* stag = (float*)(sm + FP16_ELEMS);
    const uint32_t smb = smem_u32(sm);
    const uint32_t stb = smem_u32(stag);

    const int tid  = threadIdx.x;
    const int wid  = tid >> 5;
    const int lane = tid & 31;
    const int m0   = blockIdx.x * 128;
    const int wm = (wid >> 1) * 32;
    const int wn = (wid & 1) * 64;

    float acc[2][8][4];
#pragma unroll
    for (int i = 0; i < 2; i++)
#pragma unroll
        for (int j = 0; j < 8; j++)
#pragma unroll
            for (int q = 0; q < 4; q++) acc[i][j][q] = 0.f;

    const int arow  = tid >> 1;
    const int ahalf = tid & 1;
    int rg = m0 + arow;
    if (rg >= N_NODES) rg = N_NODES - 1;
    const float* xrow = x + (size_t)rg * NFEAT + ahalf * 16;
    const uint16_t* bhrow = g_w1t_hi + (size_t)arow * NFEAT + ahalf * 16;
    const uint16_t* blrow = g_w1t_lo + (size_t)arow * NFEAT + ahalf * 16;
    const int stA  = arow * LDAF + ahalf * 16;
    const int dstA = AF16 + arow * LDA + ahalf * 16;
    const int dstB = arow * LDA + ahalf * 16;

    const int lrow = (lane & 7) + ((lane >> 3) & 1) * 8;
    const int lkof = (lane >> 4) * 8;
    const uint32_t aAddr0 = smb + (uint32_t)((AF16 + (wm + lrow) * LDA + lkof) * 2);
    const uint32_t bRel   = (uint32_t)(((wn + lrow) * LDA + lkof) * 2);

#define COPY_A(c, st) do {                                                    \
        uint32_t da = stb + ((st) * STAGF + stA) * 4;                         \
        _Pragma("unroll")                                                     \
        for (int j = 0; j < 4; ++j)                                           \
            cp_async16(da + j * 16, xrow + (c) * 32 + j * 4);                 \
        CP_COMMIT();                                                          \
    } while (0)

#define COPY_B(c, buf) do {                                                   \
        uint32_t dh = smb + (BBUF(buf) + dstB) * 2;                           \
        uint32_t dl = dh + 5120 * 2;                                          \
        _Pragma("unroll")                                                     \
        for (int j = 0; j < 2; ++j) {                                         \
            cp_async16(dh + j * 16, bhrow + (c) * 32 + j * 8);                \
            cp_async16(dl + j * 16, blrow + (c) * 32 + j * 8);                \
        }                                                                     \
        CP_COMMIT();                                                          \
    } while (0)

#define CONV_A(st) do {                                                       \
        const float* sf = stag + (st) * STAGF + stA;                          \
        float4 v0 = *(const float4*)(sf);                                     \
        float4 v1 = *(const float4*)(sf + 4);                                 \
        float4 v2 = *(const float4*)(sf + 8);                                 \
        float4 v3 = *(const float4*)(sf + 12);                                \
        uint32_t H[8];                                                        \
        H[0] = pack_f16x2(v0.x, v0.y); H[1] = pack_f16x2(v0.z, v0.w);         \
        H[2] = pack_f16x2(v1.x, v1.y); H[3] = pack_f16x2(v1.z, v1.w);         \
        H[4] = pack_f16x2(v2.x, v2.y); H[5] = pack_f16x2(v2.z, v2.w);         \
        H[6] = pack_f16x2(v3.x, v3.y); H[7] = pack_f16x2(v3.z, v3.w);         \
        uint16_t* dh = sm + dstA;                                             \
        *(uint4*)(dh)     = *(uint4*)&H[0];                                   \
        *(uint4*)(dh + 8) = *(uint4*)&H[4];                                   \
    } while (0)

    COPY_A(0, 0);
    COPY_B(0, 0);
    COPY_A(1, 1);
    COPY_B(1, 1);

#pragma unroll 1
    for (int c = 0; c < 16; ++c) {
        if (c < 14) COPY_A(c + 2, (c + 2) % 3);

        if (c < 14)       CP_WAIT3();
        else if (c == 14) CP_WAIT2();
        else              CP_WAIT0();

        CONV_A(c % 3);
        __syncthreads();

        const uint32_t bHi = smb + (uint32_t)(BBUF(c & 1) * 2) + bRel;
        const uint32_t bLo = bHi + 5120 * 2;
#pragma unroll
        for (int ks = 0; ks < 2; ++ks) {
            const uint32_t kb = ks * 32;
            uint32_t a0[4], a1[4];
            LDSM4(a0[0], a0[1], a0[2], a0[3], aAddr0 + kb);
            LDSM4(a1[0], a1[1], a1[2], a1[3], aAddr0 + 16 * LDA * 2 + kb);
#pragma unroll
            for (int ntp = 0; ntp < 4; ++ntp) {
                const uint32_t boff = (uint32_t)(ntp * 16 * LDA * 2) + kb;
                uint32_t bh[4], bl[4];
                LDSM4(bh[0], bh[1], bh[2], bh[3], bHi + boff);
                LDSM4(bl[0], bl[1], bl[2], bl[3], bLo + boff);
                float* c00 = acc[0][ntp * 2];
                float* c01 = acc[0][ntp * 2 + 1];
                float* c10 = acc[1][ntp * 2];
                float* c11 = acc[1][ntp * 2 + 1];
                mma_f16(c00, a0, bh[0], bh[2]);
                mma_f16(c01, a0, bh[1], bh[3]);
                mma_f16(c10, a1, bh[0], bh[2]);
                mma_f16(c11, a1, bh[1], bh[3]);
                mma_f16(c00, a0, bl[0], bl[2]);
                mma_f16(c01, a0, bl[1], bl[3]);
                mma_f16(c10, a1, bl[0], bl[2]);
                mma_f16(c11, a1, bl[1], bl[3]);
            }
        }
        __syncthreads();

        if (c < 14) COPY_B(c + 2, c & 1);
    }

    // epilogue: fp16 output
#pragma unroll
    for (int mt = 0; mt < 2; ++mt) {
        int r0 = m0 + wm + mt * 16 + (lane >> 2);
        int r1 = r0 + 8;
#pragma unroll
        for (int nt = 0; nt < 8; ++nt) {
            int cc = wn + nt * 8 + (lane & 3) * 2;
            if (r0 < N_NODES)
                *(uint32_t*)(out + (size_t)r0 * NHID + cc) =
                    pack_f16x2(acc[mt][nt][0], acc[mt][nt][1]);
            if (r1 < N_NODES)
                *(uint32_t*)(out + (size_t)r1 * NHID + cc) =
                    pack_f16x2(acc[mt][nt][2], acc[mt][nt][3]);
        }
    }
}

// ---------------------------------------------------------------------------
// SpMM: warp per row, row_ptr, 4-edge unroll, fp16 h (half the gather bytes).
// Lane owns 4 features: uint2 load = 4 halves.
// ---------------------------------------------------------------------------
template <bool RELU>
__global__ __launch_bounds__(256) void spmm_kernel(const int* __restrict__ cols,
                                                   const float* __restrict__ vals,
                                                   const uint16_t* __restrict__ hin,
                                                   const float* __restrict__ bias,
                                                   uint16_t* __restrict__ hout)
{
    const int gw   = (blockIdx.x * blockDim.x + threadIdx.x) >> 5;
    const int lane = threadIdx.x & 31;
    if (gw >= N_NODES) return;

    const int start = g_rowptr[gw];
    const int end   = g_rowptr[gw + 1];

    float ax = 0.f, ay = 0.f, az = 0.f, aw = 0.f;
    int e = start;
    for (; e + 4 <= end; e += 4) {
        int   c0 = cols[e],     c1 = cols[e + 1], c2 = cols[e + 2], c3 = cols[e + 3];
        float v0 = vals[e],     v1 = vals[e + 1], v2 = vals[e + 2], v3 = vals[e + 3];
        uint2 p0 = *(const uint2*)(hin + (size_t)c0 * NHID + lane * 4);
        uint2 p1 = *(const uint2*)(hin + (size_t)c1 * NHID + lane * 4);
        uint2 p2 = *(const uint2*)(hin + (size_t)c2 * NHID + lane * 4);
        uint2 p3 = *(const uint2*)(hin + (size_t)c3 * NHID + lane * 4);
        float2 f;
        f = __half22float2(*(__half2*)&p0.x); ax = fmaf(v0, f.x, ax); ay = fmaf(v0, f.y, ay);
        f = __half22float2(*(__half2*)&p0.y); az = fmaf(v0, f.x, az); aw = fmaf(v0, f.y, aw);
        f = __half22float2(*(__half2*)&p1.x); ax = fmaf(v1, f.x, ax); ay = fmaf(v1, f.y, ay);
        f = __half22float2(*(__half2*)&p1.y); az = fmaf(v1, f.x, az); aw = fmaf(v1, f.y, aw);
        f = __half22float2(*(__half2*)&p2.x); ax = fmaf(v2, f.x, ax); ay = fmaf(v2, f.y, ay);
        f = __half22float2(*(__half2*)&p2.y); az = fmaf(v2, f.x, az); aw = fmaf(v2, f.y, aw);
        f = __half22float2(*(__half2*)&p3.x); ax = fmaf(v3, f.x, ax); ay = fmaf(v3, f.y, ay);
        f = __half22float2(*(__half2*)&p3.y); az = fmaf(v3, f.x, az); aw = fmaf(v3, f.y, aw);
    }
    for (; e < end; ++e) {
        int   c0 = cols[e];
        float v0 = vals[e];
        uint2 p0 = *(const uint2*)(hin + (size_t)c0 * NHID + lane * 4);
        float2 f;
        f = __half22float2(*(__half2*)&p0.x); ax = fmaf(v0, f.x, ax); ay = fmaf(v0, f.y, ay);
        f = __half22float2(*(__half2*)&p0.y); az = fmaf(v0, f.x, az); aw = fmaf(v0, f.y, aw);
    }
    if (RELU) {
        float4 b = ((const float4*)bias)[lane];
        ax = fmaxf(ax + b.x, 0.f); ay = fmaxf(ay + b.y, 0.f);
        az = fmaxf(az + b.z, 0.f); aw = fmaxf(aw + b.w, 0.f);
    }
    uint2 st;
    st.x = pack_f16x2(ax, ay);
    st.y = pack_f16x2(az, aw);
    *(uint2*)(hout + (size_t)gw * NHID + lane * 4) = st;
}

// ---------------------------------------------------------------------------
// GEMM2: fp16 2-term (A = fp16 h, exact; B = W2^T hi/lo fp16) + fused
// bias + log_softmax. CTA 64 rows, 128 threads (4 warps; warp = 16 rows).
// SMEM (uint16): A 64x136 @0 | WH 64x136 @8704 | WL 64x136 @17408.
// ---------------------------------------------------------------------------
#define LDH 136
#define G2_A  0
#define G2_WH 8704
#define G2_WL 17408
#define SMEM_G2_BYTES (26112 * 2)   // 52224

__global__ __launch_bounds__(128) void gemm2_mma_kernel(const uint16_t* __restrict__ h,
                                                        const float* __restrict__ b2,
                                                        float* __restrict__ out)
{
    extern __shared__ uint16_t s2[];

    const int tid  = threadIdx.x;
    const int lane = tid & 31;
    const int wid  = tid >> 5;
    const int r0   = blockIdx.x * 64;

    const int row = tid >> 1, half = tid & 1;
    int rg = r0 + row;
    if (rg >= N_NODES) rg = N_NODES - 1;

    // A: copy 64 halves (128 B) per thread, no conversion
    {
        const uint16_t* hp = h + (size_t)rg * NHID + half * 64;
        uint16_t* dp = s2 + G2_A + row * LDH + half * 64;
#pragma unroll
        for (int j = 0; j < 8; ++j)
            *(uint4*)(dp + j * 8) = *(const uint4*)(hp + j * 8);
    }
    // W2^T hi/lo
    {
        const int n = row;
        const uint16_t* wh = g_w2t_hi + n * NHID + half * 64;
        const uint16_t* wl = g_w2t_lo + n * NHID + half * 64;
        uint16_t* dh = s2 + G2_WH + n * LDH + half * 64;
        uint16_t* dl = s2 + G2_WL + n * LDH + half * 64;
#pragma unroll
        for (int j = 0; j < 8; ++j) {
            *(uint4*)(dh + j * 8) = *(const uint4*)(wh + j * 8);
            *(uint4*)(dl + j * 8) = *(const uint4*)(wl + j * 8);
        }
    }
    __syncthreads();

    float acc[8][4];
#pragma unroll
    for (int nt = 0; nt < 8; ++nt)
#pragma unroll
        for (int q = 0; q < 4; ++q) acc[nt][q] = 0.f;

    const int wr = wid * 16;
#pragma unroll
    for (int ks = 0; ks < 8; ++ks) {
        const int kk = ks * 16;
        const int r  = wr + (lane >> 2);
        const int cc = kk + (lane & 3) * 2;
        uint32_t a[4];
        a[0] = *(const uint32_t*)(s2 + G2_A + r * LDH + cc);
        a[1] = *(const uint32_t*)(s2 + G2_A + (r + 8) * LDH + cc);
        a[2] = *(const uint32_t*)(s2 + G2_A + r * LDH + cc + 8);
        a[3] = *(const uint32_t*)(s2 + G2_A + (r + 8) * LDH + cc + 8);
#pragma unroll
        for (int nt = 0; nt < 8; ++nt) {
            int n  = nt * 8 + (lane >> 2);
            int kq = kk + (lane & 3) * 2;
            uint32_t bh0 = *(const uint32_t*)(s2 + G2_WH + n * LDH + kq);
            uint32_t bh1 = *(const uint32_t*)(s2 + G2_WH + n * LDH + kq + 8);
            uint32_t bl0 = *(const uint32_t*)(s2 + G2_WL + n * LDH + kq);
            uint32_t bl1 = *(const uint32_t*)(s2 + G2_WL + n * LDH + kq + 8);
            mma_f16(acc[nt], a, bh0, bh1);
            mma_f16(acc[nt], a, bl0, bl1);
        }
    }

#pragma unroll
    for (int nt = 0; nt < 8; ++nt) {
        int c = nt * 8 + (lane & 3) * 2;
        float bb0 = b2[c], bb1 = b2[c + 1];
        acc[nt][0] += bb0; acc[nt][1] += bb1;
        acc[nt][2] += bb0; acc[nt][3] += bb1;
    }

    float m0 = -1e30f, m1 = -1e30f;
#pragma unroll
    for (int nt = 0; nt < 8; ++nt) {
        m0 = fmaxf(m0, fmaxf(acc[nt][0], acc[nt][1]));
        m1 = fmaxf(m1, fmaxf(acc[nt][2], acc[nt][3]));
    }
    m0 = fmaxf(m0, __shfl_xor_sync(0xffffffffu, m0, 1));
    m0 = fmaxf(m0, __shfl_xor_sync(0xffffffffu, m0, 2));
    m1 = fmaxf(m1, __shfl_xor_sync(0xffffffffu, m1, 1));
    m1 = fmaxf(m1, __shfl_xor_sync(0xffffffffu, m1, 2));

    float s0 = 0.f, s1 = 0.f;
#pragma unroll
    for (int nt = 0; nt < 8; ++nt) {
        s0 += expf(acc[nt][0] - m0) + expf(acc[nt][1] - m0);
        s1 += expf(acc[nt][2] - m1) + expf(acc[nt][3] - m1);
    }
    s0 += __shfl_xor_sync(0xffffffffu, s0, 1);
    s0 += __shfl_xor_sync(0xffffffffu, s0, 2);
    s1 += __shfl_xor_sync(0xffffffffu, s1, 1);
    s1 += __shfl_xor_sync(0xffffffffu, s1, 2);
    const float lse0 = m0 + logf(s0);
    const float lse1 = m1 + logf(s1);

    const int row0 = r0 + wr + (lane >> 2);
    const int row1 = row0 + 8;
#pragma unroll
    for (int nt = 0; nt < 8; ++nt) {
        int c = nt * 8 + (lane & 3) * 2;
        if (row0 < N_NODES)
            *(float2*)(out + (size_t)row0 * NCLASS + c) =
                make_float2(acc[nt][0] - lse0, acc[nt][1] - lse0);
        if (row1 < N_NODES)
            *(float2*)(out + (size_t)row1 * NCLASS + c) =
                make_float2(acc[nt][2] - lse1, acc[nt][3] - lse1);
    }
}

// ---------------------------------------------------------------------------
extern "C" void kernel_launch(void* const* d_in, const int* in_sizes, int n_in,
                              void* d_out, int out_size)
{
    const float* x    = (const float*)d_in[0];
    const int*   rows = (const int*)  d_in[1];
    const int*   cols = (const int*)  d_in[2];
    const float* vals = (const float*)d_in[3];
    const float* W1   = (const float*)d_in[4];
    const float* b1   = (const float*)d_in[5];
    const float* W2   = (const float*)d_in[6];
    const float* b2   = (const float*)d_in[7];
    float* out = (float*)d_out;

    uint16_t *h0, *h1;
    cudaGetSymbolAddress((void**)&h0, g_h0);
    cudaGetSymbolAddress((void**)&h1, g_h1);

    cudaFuncSetAttribute(gemm1_mma_kernel, cudaFuncAttributeMaxDynamicSharedMemorySize, SMEM_G1_BYTES);
    cudaFuncSetAttribute(gemm2_mma_kernel, cudaFuncAttributeMaxDynamicSharedMemorySize, SMEM_G2_BYTES);

    // 0) prep
    prep_w1_kernel<<<(NHID * NFEAT / 2 + 255) / 256, 256>>>(W1);
    prep_w2_kernel<<<(NCLASS * NHID / 2 + 255) / 256, 256>>>(W2);
    rowptr_kernel<<<(N_EDGES + 255) / 256, 256>>>(rows);

    // 1) h0 = X @ W1  (fp16 out)
    gemm1_mma_kernel<<<(N_NODES + 127) / 128, 256, SMEM_G1_BYTES>>>(x, h0);

    // 2) h1 = relu(A @ h0 + b1)   (fp16 gather + fp16 out)
    const int spmm_blocks = (N_NODES * 32 + 255) / 256;
    spmm_kernel<true><<<spmm_blocks, 256>>>(cols, vals, h0, b1, h1);

    // 3) h0 <- A @ h1
    spmm_kernel<false><<<spmm_blocks, 256>>>(cols, vals, h1, b1, h0);

    // 4) out = logsoftmax(h0 @ W2 + b2)
    gemm2_mma_kernel<<<(N_NODES + 63) / 64, 128, SMEM_G2_BYTES>>>(h0, b2, out);
}

// round 13
// speedup vs baseline: 1.3454x; 1.0279x over previous
#include <cuda_runtime.h>
#include <cuda_fp16.h>
#include <math.h>
#include <stdint.h>

#define N_NODES 50000
#define N_EDGES 800000
#define NFEAT   512
#define NHID    128
#define NCLASS  64

// Scratch (allocation-free) — h0/h1 fp16
__device__ uint16_t g_h0[(size_t)N_NODES * NHID];
__device__ uint16_t g_h1[(size_t)N_NODES * NHID];
__device__ uint16_t g_w1t_hi[NHID * NFEAT];   // W1^T hi fp16 [n][k]
__device__ uint16_t g_w1t_lo[NHID * NFEAT];   // W1^T lo fp16 [n][k]
__device__ uint16_t g_w2t_hi[NCLASS * NHID];  // W2^T hi fp16 [n][k]
__device__ uint16_t g_w2t_lo[NCLASS * NHID];  // W2^T lo fp16 [n][k]
__device__ int g_rowptr[N_NODES + 1];

// ---------------------------------------------------------------------------
// helpers
// ---------------------------------------------------------------------------
__device__ __forceinline__ uint32_t smem_u32(const void* p) {
    uint32_t a;
    asm("{ .reg .u64 t; cvta.to.shared.u64 t, %1; cvt.u32.u64 %0, t; }" : "=r"(a) : "l"(p));
    return a;
}
__device__ __forceinline__ uint32_t pack_f16x2(float lo, float hi) {
    uint32_t r;
    asm("cvt.rn.f16x2.f32 %0, %1, %2;" : "=r"(r) : "f"(hi), "f"(lo));
    return r;
}
__device__ __forceinline__ float f16_lo_f32(uint32_t p) {
    float f; asm("{ .reg .f16 h; mov.b32 {h, _}, %1; cvt.f32.f16 %0, h; }" : "=f"(f) : "r"(p));
    return f;
}
__device__ __forceinline__ float f16_hi_f32(uint32_t p) {
    float f; asm("{ .reg .f16 h; mov.b32 {_, h}, %1; cvt.f32.f16 %0, h; }" : "=f"(f) : "r"(p));
    return f;
}

__device__ __forceinline__ void mma_f16(float* d, const uint32_t* a,
                                        uint32_t b0, uint32_t b1) {
    asm("mma.sync.aligned.m16n8k16.row.col.f32.f16.f16.f32 "
        "{%0,%1,%2,%3}, {%4,%5,%6,%7}, {%8,%9}, {%0,%1,%2,%3};"
        : "+f"(d[0]), "+f"(d[1]), "+f"(d[2]), "+f"(d[3])
        : "r"(a[0]), "r"(a[1]), "r"(a[2]), "r"(a[3]), "r"(b0), "r"(b1));
}
#define LDSM4(r0, r1, r2, r3, addr) \
    asm volatile("ldmatrix.sync.aligned.m8n8.x4.shared.b16 {%0,%1,%2,%3}, [%4];" \
        : "=r"(r0), "=r"(r1), "=r"(r2), "=r"(r3) : "r"(addr))

__device__ __forceinline__ void cp_async16(uint32_t dst, const void* src) {
    asm volatile("cp.async.cg.shared.global [%0], [%1], 16;" :: "r"(dst), "l"(src));
}
#define CP_COMMIT() asm volatile("cp.async.commit_group;" ::: "memory")
#define CP_WAIT0()  asm volatile("cp.async.wait_group 0;" ::: "memory")
#define CP_WAIT2()  asm volatile("cp.async.wait_group 2;" ::: "memory")
#define CP_WAIT3()  asm volatile("cp.async.wait_group 3;" ::: "memory")

// ---------------------------------------------------------------------------
// prep kernels
// ---------------------------------------------------------------------------
__global__ void prep_w1_kernel(const float* __restrict__ W1) {
    int idx = blockIdx.x * 256 + threadIdx.x;
    if (idx >= NHID * NFEAT / 2) return;
    int n = idx >> 8;
    int k2 = (idx & 255) * 2;
    float w0 = W1[(size_t)k2 * NHID + n];
    float w1 = W1[(size_t)(k2 + 1) * NHID + n];
    uint32_t ph = pack_f16x2(w0, w1);
    uint32_t pl = pack_f16x2(w0 - f16_lo_f32(ph), w1 - f16_hi_f32(ph));
    *(uint32_t*)&g_w1t_hi[n * NFEAT + k2] = ph;
    *(uint32_t*)&g_w1t_lo[n * NFEAT + k2] = pl;
}

__global__ void prep_w2_kernel(const float* __restrict__ W2) {
    int idx = blockIdx.x * 256 + threadIdx.x;
    if (idx >= NCLASS * NHID / 2) return;
    int n = idx >> 6;
    int k2 = (idx & 63) * 2;
    float w0 = W2[(size_t)k2 * NCLASS + n];
    float w1 = W2[(size_t)(k2 + 1) * NCLASS + n];
    uint32_t ph = pack_f16x2(w0, w1);
    uint32_t pl = pack_f16x2(w0 - f16_lo_f32(ph), w1 - f16_hi_f32(ph));
    *(uint32_t*)&g_w2t_hi[n * NHID + k2] = ph;
    *(uint32_t*)&g_w2t_lo[n * NHID + k2] = pl;
}

__global__ void rowptr_kernel(const int* __restrict__ rows) {
    int e = blockIdx.x * 256 + threadIdx.x;
    if (e >= N_EDGES) return;
    int r = rows[e];
    int rp = (e == 0) ? -1 : rows[e - 1];
    for (int q = rp + 1; q <= r; ++q) g_rowptr[q] = e;
    if (e == N_EDGES - 1)
        for (int q = r + 1; q <= N_NODES; ++q) g_rowptr[q] = N_EDGES;
}

// ---------------------------------------------------------------------------
// GEMM1: fp16 2-term, depth-2 async pipeline, ldmatrix, 512 threads.
// CTA 128x128, 16 warps (8M x 2N), warp tile 16x64, BK=32.
// ---------------------------------------------------------------------------
#define LDA   40
#define AF16  0
#define BBUF(b) (5120 + (b) * 10240)
#define FP16_ELEMS 25600
#define LDAF  36
#define STAGF 4608
#define SMEM_G1_BYTES (FP16_ELEMS * 2 + 3 * STAGF * 4)   // 106496

__global__ __launch_bounds__(512, 2) void gemm1_mma_kernel(const float* __restrict__ x,
                                                           uint16_t* __restrict__ out)
{
    extern __shared__ uint16_t sm[];
    float* stag = (float*)(sm + FP16_ELEMS);
    const uint32_t smb = smem_u32(sm);
    const uint32_t stb = smem_u32(stag);

    const int tid  = threadIdx.x;
    const int wid  = tid >> 5;        // 0..15
    const int lane = tid & 31;
    const int m0   = blockIdx.x * 128;
    const int wm = (wid >> 1) * 16;   // 0..112
    const int wn = (wid & 1) * 64;    // 0,64

    float acc[8][4];
#pragma unroll
    for (int j = 0; j < 8; j++)
#pragma unroll
        for (int q = 0; q < 4; q++) acc[j][q] = 0.f;

    // copy mapping: 4 threads per row, 8 elems each
    const int arow = tid >> 2;        // 0..127
    const int aq   = tid & 3;         // 0..3
    int rg = m0 + arow;
    if (rg >= N_NODES) rg = N_NODES - 1;
    const float* xrow = x + (size_t)rg * NFEAT + aq * 8;
    const uint16_t* bhrow = g_w1t_hi + (size_t)arow * NFEAT + aq * 8;
    const uint16_t* blrow = g_w1t_lo + (size_t)arow * NFEAT + aq * 8;
    const int stA  = arow * LDAF + aq * 8;        // fp32 elems
    const int dstA = AF16 + arow * LDA + aq * 8;  // fp16 elems
    const int dstB = arow * LDA + aq * 8;         // fp16 elems

    const int lrow = (lane & 7) + ((lane >> 3) & 1) * 8;
    const int lkof = (lane >> 4) * 8;
    const uint32_t aAddr0 = smb + (uint32_t)((AF16 + (wm + lrow) * LDA + lkof) * 2);
    const uint32_t bRel   = (uint32_t)(((wn + lrow) * LDA + lkof) * 2);

#define COPY_A(c, st) do {                                                    \
        uint32_t da = stb + ((st) * STAGF + stA) * 4;                         \
        cp_async16(da,      xrow + (c) * 32);                                 \
        cp_async16(da + 16, xrow + (c) * 32 + 4);                             \
        CP_COMMIT();                                                          \
    } while (0)

#define COPY_B(c, buf) do {                                                   \
        uint32_t dh = smb + (BBUF(buf) + dstB) * 2;                           \
        uint32_t dl = dh + 5120 * 2;                                          \
        cp_async16(dh, bhrow + (c) * 32);                                     \
        cp_async16(dl, blrow + (c) * 32);                                     \
        CP_COMMIT();                                                          \
    } while (0)

#define CONV_A(st) do {                                                       \
        const float* sf = stag + (st) * STAGF + stA;                          \
        float4 v0 = *(const float4*)(sf);                                     \
        float4 v1 = *(const float4*)(sf + 4);                                 \
        uint32_t H[4];                                                        \
        H[0] = pack_f16x2(v0.x, v0.y); H[1] = pack_f16x2(v0.z, v0.w);         \
        H[2] = pack_f16x2(v1.x, v1.y); H[3] = pack_f16x2(v1.z, v1.w);         \
        *(uint4*)(sm + dstA) = *(uint4*)&H[0];                                \
    } while (0)

    COPY_A(0, 0);
    COPY_B(0, 0);
    COPY_A(1, 1);
    COPY_B(1, 1);

#pragma unroll 1
    for (int c = 0; c < 16; ++c) {
        if (c < 14) COPY_A(c + 2, (c + 2) % 3);

        if (c < 14)       CP_WAIT3();
        else if (c == 14) CP_WAIT2();
        else              CP_WAIT0();

        CONV_A(c % 3);
        __syncthreads();

        const uint32_t bHi = smb + (uint32_t)(BBUF(c & 1) * 2) + bRel;
        const uint32_t bLo = bHi + 5120 * 2;
#pragma unroll
        for (int ks = 0; ks < 2; ++ks) {
            const uint32_t kb = ks * 32;
            uint32_t a0[4];
            LDSM4(a0[0], a0[1], a0[2], a0[3], aAddr0 + kb);
#pragma unroll
            for (int ntp = 0; ntp < 4; ++ntp) {
                const uint32_t boff = (uint32_t)(ntp * 16 * LDA * 2) + kb;
                uint32_t bh[4], bl[4];
                LDSM4(bh[0], bh[1], bh[2], bh[3], bHi + boff);
                LDSM4(bl[0], bl[1], bl[2], bl[3], bLo + boff);
                float* c0 = acc[ntp * 2];
                float* c1 = acc[ntp * 2 + 1];
                mma_f16(c0, a0, bh[0], bh[2]);
                mma_f16(c1, a0, bh[1], bh[3]);
                mma_f16(c0, a0, bl[0], bl[2]);
                mma_f16(c1, a0, bl[1], bl[3]);
            }
        }
        __syncthreads();

        if (c < 14) COPY_B(c + 2, c & 1);
    }

    // epilogue: fp16 output
    {
        int r0 = m0 + wm + (lane >> 2);
        int r1 = r0 + 8;
#pragma unroll
        for (int nt = 0; nt < 8; ++nt) {
            int cc = wn + nt * 8 + (lane & 3) * 2;
            if (r0 < N_NODES)
                *(uint32_t*)(out + (size_t)r0 * NHID + cc) =
                    pack_f16x2(acc[nt][0], acc[nt][1]);
            if (r1 < N_NODES)
                *(uint32_t*)(out + (size_t)r1 * NHID + cc) =
                    pack_f16x2(acc[nt][2], acc[nt][3]);
        }
    }
}

// ---------------------------------------------------------------------------
// SpMM: warp per row, row_ptr, 4-edge unroll, fp16 h. (R12, kept)
// ---------------------------------------------------------------------------
template <bool RELU>
__global__ __launch_bounds__(256) void spmm_kernel(const int* __restrict__ cols,
                                                   const float* __restrict__ vals,
                                                   const uint16_t* __restrict__ hin,
                                                   const float* __restrict__ bias,
                                                   uint16_t* __restrict__ hout)
{
    const int gw   = (blockIdx.x * blockDim.x + threadIdx.x) >> 5;
    const int lane = threadIdx.x & 31;
    if (gw >= N_NODES) return;

    const int start = g_rowptr[gw];
    const int end   = g_rowptr[gw + 1];

    float ax = 0.f, ay = 0.f, az = 0.f, aw = 0.f;
    int e = start;
    for (; e + 4 <= end; e += 4) {
        int   c0 = cols[e],     c1 = cols[e + 1], c2 = cols[e + 2], c3 = cols[e + 3];
        float v0 = vals[e],     v1 = vals[e + 1], v2 = vals[e + 2], v3 = vals[e + 3];
        uint2 p0 = *(const uint2*)(hin + (size_t)c0 * NHID + lane * 4);
        uint2 p1 = *(const uint2*)(hin + (size_t)c1 * NHID + lane * 4);
        uint2 p2 = *(const uint2*)(hin + (size_t)c2 * NHID + lane * 4);
        uint2 p3 = *(const uint2*)(hin + (size_t)c3 * NHID + lane * 4);
        float2 f;
        f = __half22float2(*(__half2*)&p0.x); ax = fmaf(v0, f.x, ax); ay = fmaf(v0, f.y, ay);
        f = __half22float2(*(__half2*)&p0.y); az = fmaf(v0, f.x, az); aw = fmaf(v0, f.y, aw);
        f = __half22float2(*(__half2*)&p1.x); ax = fmaf(v1, f.x, ax); ay = fmaf(v1, f.y, ay);
        f = __half22float2(*(__half2*)&p1.y); az = fmaf(v1, f.x, az); aw = fmaf(v1, f.y, aw);
        f = __half22float2(*(__half2*)&p2.x); ax = fmaf(v2, f.x, ax); ay = fmaf(v2, f.y, ay);
        f = __half22float2(*(__half2*)&p2.y); az = fmaf(v2, f.x, az); aw = fmaf(v2, f.y, aw);
        f = __half22float2(*(__half2*)&p3.x); ax = fmaf(v3, f.x, ax); ay = fmaf(v3, f.y, ay);
        f = __half22float2(*(__half2*)&p3.y); az = fmaf(v3, f.x, az); aw = fmaf(v3, f.y, aw);
    }
    for (; e < end; ++e) {
        int   c0 = cols[e];
        float v0 = vals[e];
        uint2 p0 = *(const uint2*)(hin + (size_t)c0 * NHID + lane * 4);
        float2 f;
        f = __half22float2(*(__half2*)&p0.x); ax = fmaf(v0, f.x, ax); ay = fmaf(v0, f.y, ay);
        f = __half22float2(*(__half2*)&p0.y); az = fmaf(v0, f.x, az); aw = fmaf(v0, f.y, aw);
    }
    if (RELU) {
        float4 b = ((const float4*)bias)[lane];
        ax = fmaxf(ax + b.x, 0.f); ay = fmaxf(ay + b.y, 0.f);
        az = fmaxf(az + b.z, 0.f); aw = fmaxf(aw + b.w, 0.f);
    }
    uint2 st;
    st.x = pack_f16x2(ax, ay);
    st.y = pack_f16x2(az, aw);
    *(uint2*)(hout + (size_t)gw * NHID + lane * 4) = st;
}

// ---------------------------------------------------------------------------
// GEMM2: fp16 2-term + fused bias + log_softmax. (R12, kept)
// ---------------------------------------------------------------------------
#define LDH 136
#define G2_A  0
#define G2_WH 8704
#define G2_WL 17408
#define SMEM_G2_BYTES (26112 * 2)   // 52224

__global__ __launch_bounds__(128) void gemm2_mma_kernel(const uint16_t* __restrict__ h,
                                                        const float* __restrict__ b2,
                                                        float* __restrict__ out)
{
    extern __shared__ uint16_t s2[];

    const int tid  = threadIdx.x;
    const int lane = tid & 31;
    const int wid  = tid >> 5;
    const int r0   = blockIdx.x * 64;

    const int row = tid >> 1, half = tid & 1;
    int rg = r0 + row;
    if (rg >= N_NODES) rg = N_NODES - 1;

    {
        const uint16_t* hp = h + (size_t)rg * NHID + half * 64;
        uint16_t* dp = s2 + G2_A + row * LDH + half * 64;
#pragma unroll
        for (int j = 0; j < 8; ++j)
            *(uint4*)(dp + j * 8) = *(const uint4*)(hp + j * 8);
    }
    {
        const int n = row;
        const uint16_t* wh = g_w2t_hi + n * NHID + half * 64;
        const uint16_t* wl = g_w2t_lo + n * NHID + half * 64;
        uint16_t* dh = s2 + G2_WH + n * LDH + half * 64;
        uint16_t* dl = s2 + G2_WL + n * LDH + half * 64;
#pragma unroll
        for (int j = 0; j < 8; ++j) {
            *(uint4*)(dh + j * 8) = *(const uint4*)(wh + j * 8);
            *(uint4*)(dl + j * 8) = *(const uint4*)(wl + j * 8);
        }
    }
    __syncthreads();

    float acc[8][4];
#pragma unroll
    for (int nt = 0; nt < 8; ++nt)
#pragma unroll
        for (int q = 0; q < 4; ++q) acc[nt][q] = 0.f;

    const int wr = wid * 16;
#pragma unroll
    for (int ks = 0; ks < 8; ++ks) {
        const int kk = ks * 16;
        const int r  = wr + (lane >> 2);
        const int cc = kk + (lane & 3) * 2;
        uint32_t a[4];
        a[0] = *(const uint32_t*)(s2 + G2_A + r * LDH + cc);
        a[1] = *(const uint32_t*)(s2 + G2_A + (r + 8) * LDH + cc);
        a[2] = *(const uint32_t*)(s2 + G2_A + r * LDH + cc + 8);
        a[3] = *(const uint32_t*)(s2 + G2_A + (r + 8) * LDH + cc + 8);
#pragma unroll
        for (int nt = 0; nt < 8; ++nt) {
            int n  = nt * 8 + (lane >> 2);
            int kq = kk + (lane & 3) * 2;
            uint32_t bh0 = *(const uint32_t*)(s2 + G2_WH + n * LDH + kq);
            uint32_t bh1 = *(const uint32_t*)(s2 + G2_WH + n * LDH + kq + 8);
            uint32_t bl0 = *(const uint32_t*)(s2 + G2_WL + n * LDH + kq);
            uint32_t bl1 = *(const uint32_t*)(s2 + G2_WL + n * LDH + kq + 8);
            mma_f16(acc[nt], a, bh0, bh1);
            mma_f16(acc[nt], a, bl0, bl1);
        }
    }

#pragma unroll
    for (int nt = 0; nt < 8; ++nt) {
        int c = nt * 8 + (lane & 3) * 2;
        float bb0 = b2[c], bb1 = b2[c + 1];
        acc[nt][0] += bb0; acc[nt][1] += bb1;
        acc[nt][2] += bb0; acc[nt][3] += bb1;
    }

    float m0 = -1e30f, m1 = -1e30f;
#pragma unroll
    for (int nt = 0; nt < 8; ++nt) {
        m0 = fmaxf(m0, fmaxf(acc[nt][0], acc[nt][1]));
        m1 = fmaxf(m1, fmaxf(acc[nt][2], acc[nt][3]));
    }
    m0 = fmaxf(m0, __shfl_xor_sync(0xffffffffu, m0, 1));
    m0 = fmaxf(m0, __shfl_xor_sync(0xffffffffu, m0, 2));
    m1 = fmaxf(m1, __shfl_xor_sync(0xffffffffu, m1, 1));
    m1 = fmaxf(m1, __shfl_xor_sync(0xffffffffu, m1, 2));

    float s0 = 0.f, s1 = 0.f;
#pragma unroll
    for (int nt = 0; nt < 8; ++nt) {
        s0 += expf(acc[nt][0] - m0) + expf(acc[nt][1] - m0);
        s1 += expf(acc[nt][2] - m1) + expf(acc[nt][3] - m1);
    }
    s0 += __shfl_xor_sync(0xffffffffu, s0, 1);
    s0 += __shfl_xor_sync(0xffffffffu, s0, 2);
    s1 += __shfl_xor_sync(0xffffffffu, s1, 1);
    s1 += __shfl_xor_sync(0xffffffffu, s1, 2);
    const float lse0 = m0 + logf(s0);
    const float lse1 = m1 + logf(s1);

    const int row0 = r0 + wr + (lane >> 2);
    const int row1 = row0 + 8;
#pragma unroll
    for (int nt = 0; nt < 8; ++nt) {
        int c = nt * 8 + (lane & 3) * 2;
        if (row0 < N_NODES)
            *(float2*)(out + (size_t)row0 * NCLASS + c) =
                make_float2(acc[nt][0] - lse0, acc[nt][1] - lse0);
        if (row1 < N_NODES)
            *(float2*)(out + (size_t)row1 * NCLASS + c) =
                make_float2(acc[nt][2] - lse1, acc[nt][3] - lse1);
    }
}

// ---------------------------------------------------------------------------
extern "C" void kernel_launch(void* const* d_in, const int* in_sizes, int n_in,
                              void* d_out, int out_size)
{
    const float* x    = (const float*)d_in[0];
    const int*   rows = (const int*)  d_in[1];
    const int*   cols = (const int*)  d_in[2];
    const float* vals = (const float*)d_in[3];
    const float* W1   = (const float*)d_in[4];
    const float* b1   = (const float*)d_in[5];
    const float* W2   = (const float*)d_in[6];
    const float* b2   = (const float*)d_in[7];
    float* out = (float*)d_out;

    uint16_t *h0, *h1;
    cudaGetSymbolAddress((void**)&h0, g_h0);
    cudaGetSymbolAddress((void**)&h1, g_h1);

    cudaFuncSetAttribute(gemm1_mma_kernel, cudaFuncAttributeMaxDynamicSharedMemorySize, SMEM_G1_BYTES);
    cudaFuncSetAttribute(gemm2_mma_kernel, cudaFuncAttributeMaxDynamicSharedMemorySize, SMEM_G2_BYTES);

    // 0) prep
    prep_w1_kernel<<<(NHID * NFEAT / 2 + 255) / 256, 256>>>(W1);
    prep_w2_kernel<<<(NCLASS * NHID / 2 + 255) / 256, 256>>>(W2);
    rowptr_kernel<<<(N_EDGES + 255) / 256, 256>>>(rows);

    // 1) h0 = X @ W1  (512 threads, 16 warps)
    gemm1_mma_kernel<<<(N_NODES + 127) / 128, 512, SMEM_G1_BYTES>>>(x, h0);

    // 2) h1 = relu(A @ h0 + b1)
    const int spmm_blocks = (N_NODES * 32 + 255) / 256;
    spmm_kernel<true><<<spmm_blocks, 256>>>(cols, vals, h0, b1, h1);

    // 3) h0 <- A @ h1
    spmm_kernel<false><<<spmm_blocks, 256>>>(cols, vals, h1, b1, h0);

    // 4) out = logsoftmax(h0 @ W2 + b2)
    gemm2_mma_kernel<<<(N_NODES + 63) / 64, 128, SMEM_G2_BYTES>>>(h0, b2, out);
}